// round 8
// baseline (speedup 1.0000x reference)
#include <cuda_runtime.h>
#include <math.h>
#include <stdint.h>

// ---------------------------------------------------------------------------
// ConformerBlock: B=4, T=1024, D=512, H=8, DH=64, W1=32, WB=65, FF=2048,
// CE=1024, KS=31. Output = (out[B,T,D], probs[B,T,H,WB]) concatenated fp32.
// GEMMs: tf32 mma.sync, cp.async 2-stage pipeline.
// A operands pre-rounded to tf32 at producers; B (weights) converted in-loop.
// ---------------------------------------------------------------------------

#define CB 4
#define CT 1024
#define CD 512
#define CH 8
#define CDH 64
#define CW1 32
#define CWB 65
#define CFF 2048
#define CCE 1024
#define CKS 31
#define CEPS 1e-5f

#define NTOK (CB * CT)          // 4096 rows

// ------------------------- scratch (device globals) ------------------------
__device__ float g_ln [NTOK * CD];
__device__ float g_ff [NTOK * CFF];
__device__ float g_h  [NTOK * CD];
__device__ float g_hr [NTOK * CD];     // rounded copy of h (QKV GEMM A)
__device__ float g_h2 [NTOK * CD];
__device__ float g_q  [NTOK * CD];
__device__ float g_k  [NTOK * CD];
__device__ float g_v  [NTOK * CD];
__device__ float g_ce [NTOK * CCE];
__device__ float g_glu[NTOK * CD];
__device__ float g_dw [NTOK * CD];

// ----------------------------- tf32 helpers --------------------------------
__device__ __forceinline__ float rna_tf32(float x)
{
    uint32_t y;
    asm("cvt.rna.tf32.f32 %0, %1;" : "=r"(y) : "f"(x));
    return __uint_as_float(y);
}

__device__ __forceinline__ uint32_t to_tf32(float x)
{
    uint32_t y;
    asm("cvt.rna.tf32.f32 %0, %1;" : "=r"(y) : "f"(x));
    return y;
}

__device__ __forceinline__ void cp16(void* smem_dst, const void* gsrc)
{
    uint32_t s = (uint32_t)__cvta_generic_to_shared(smem_dst);
    asm volatile("cp.async.cg.shared.global [%0], [%1], 16;\n" :: "r"(s), "l"(gsrc));
}

#define MMA_TF32(d, a, b)                                                     \
    asm volatile(                                                             \
        "mma.sync.aligned.m16n8k8.row.col.f32.tf32.tf32.f32 "                 \
        "{%0,%1,%2,%3}, {%4,%5,%6,%7}, {%8,%9}, {%0,%1,%2,%3};"               \
        : "+f"(d[0]), "+f"(d[1]), "+f"(d[2]), "+f"(d[3])                      \
        : "r"(a[0]), "r"(a[1]), "r"(a[2]), "r"(a[3]), "r"(b[0]), "r"(b[1]))

// ------------------------------- LayerNorm ---------------------------------
// ROUND: store tf32-rounded output (when the LN result feeds a GEMM only)
template<bool ROUND>
__global__ void ln_k(const float* __restrict__ x, const float* __restrict__ g,
                     const float* __restrict__ b, float* __restrict__ y)
{
    int row = blockIdx.x;
    int tid = threadIdx.x;
    const float4* xr = reinterpret_cast<const float4*>(x + (size_t)row * CD);
    float4 v = xr[tid];

    __shared__ float red1[4];
    __shared__ float red2[4];

    float s = v.x + v.y + v.z + v.w;
    #pragma unroll
    for (int o = 16; o; o >>= 1) s += __shfl_xor_sync(0xffffffffu, s, o);
    if ((tid & 31) == 0) red1[tid >> 5] = s;
    __syncthreads();
    float mean = (red1[0] + red1[1] + red1[2] + red1[3]) * (1.0f / CD);

    float dx = v.x - mean, dy = v.y - mean, dz = v.z - mean, dw = v.w - mean;
    float ss = dx * dx + dy * dy + dz * dz + dw * dw;
    #pragma unroll
    for (int o = 16; o; o >>= 1) ss += __shfl_xor_sync(0xffffffffu, ss, o);
    if ((tid & 31) == 0) red2[tid >> 5] = ss;
    __syncthreads();
    float var = (red2[0] + red2[1] + red2[2] + red2[3]) * (1.0f / CD);
    float inv = rsqrtf(var + CEPS);

    float4 gv = reinterpret_cast<const float4*>(g)[tid];
    float4 bv = reinterpret_cast<const float4*>(b)[tid];
    float4 o4;
    o4.x = dx * inv * gv.x + bv.x;
    o4.y = dy * inv * gv.y + bv.y;
    o4.z = dz * inv * gv.z + bv.z;
    o4.w = dw * inv * gv.w + bv.w;
    if (ROUND) {
        o4.x = rna_tf32(o4.x); o4.y = rna_tf32(o4.y);
        o4.z = rna_tf32(o4.z); o4.w = rna_tf32(o4.w);
    }
    reinterpret_cast<float4*>(y + (size_t)row * CD)[tid] = o4;
}

// ------------------------------- TC GEMM core -------------------------------
// C[M=4096, N] = epilogue(A @ B + bias)
// A pre-rounded to tf32 in memory (raw bit loads); B converted in-loop.
// mode: 0 = bias, 1 = swish (store rounded), 2 = 0.125*(..), 3 = res+,
//       4 = res + 0.5* (also store rounded copy to Cr when non-null)
#define AS_STRIDE 20   // [m][k], pad 16->20: frag bank = (4g+tig)%32, distinct
#define BS_STRIDE 136  // [k][n], pad 128->136: frag bank = (8tig+g)%32, distinct

#define GEMM_LOAD_STAGE(sbuf, kbase)                                           \
    {                                                                          \
        _Pragma("unroll")                                                      \
        for (int it = 0; it < 2; it++) {                                       \
            int idx = tid + it * 256;                                          \
            cp16(&As[sbuf][(idx >> 2) * AS_STRIDE + (idx & 3) * 4],            \
                 &A[(size_t)(m0 + (idx >> 2)) * K + (kbase) + (idx & 3) * 4]); \
            cp16(&Bs[sbuf][(idx >> 5) * BS_STRIDE + (idx & 31) * 4],           \
                 &Bm[(size_t)((kbase) + (idx >> 5)) * N + n0 + (idx & 31) * 4]);\
        }                                                                      \
        asm volatile("cp.async.commit_group;\n");                              \
    }

__device__ __forceinline__ void gemm_core(
    const float* __restrict__ A, const float* __restrict__ Bm,
    const float* __restrict__ bias, const float* __restrict__ res,
    float* __restrict__ C, float* __restrict__ Cr, int N, int K, int mode)
{
    __shared__ float As[2][128 * AS_STRIDE];   // 2 x 10240 B
    __shared__ float Bs[2][16 * BS_STRIDE];    // 2 x  8704 B  (total 37.9 KB)

    const int tid  = threadIdx.x;
    const int lane = tid & 31;
    const int warp = tid >> 5;
    const int g    = lane >> 2;
    const int tig  = lane & 3;

    const int m0 = blockIdx.y * 128;
    const int n0 = blockIdx.x * 128;
    const int wm = (warp & 1) * 64;
    const int wn = (warp >> 1) * 32;

    float acc[4][4][4];
    #pragma unroll
    for (int mt = 0; mt < 4; mt++)
        #pragma unroll
        for (int nt = 0; nt < 4; nt++)
            #pragma unroll
            for (int i = 0; i < 4; i++) acc[mt][nt][i] = 0.0f;

    GEMM_LOAD_STAGE(0, 0);

    const int niter = K >> 4;
    for (int i = 0; i < niter; i++) {
        asm volatile("cp.async.wait_group 0;\n");
        __syncthreads();
        if (i + 1 < niter) GEMM_LOAD_STAGE((i + 1) & 1, (i + 1) << 4);

        const float* as = As[i & 1];
        const float* bs = Bs[i & 1];
        #pragma unroll
        for (int ks = 0; ks < 2; ks++) {
            const int kk = ks * 8;
            uint32_t bfrag[4][2];
            #pragma unroll
            for (int nt = 0; nt < 4; nt++) {
                int col = wn + nt * 8 + g;
                bfrag[nt][0] = to_tf32(bs[(kk + tig)     * BS_STRIDE + col]);
                bfrag[nt][1] = to_tf32(bs[(kk + tig + 4) * BS_STRIDE + col]);
            }
            #pragma unroll
            for (int mt = 0; mt < 4; mt++) {
                uint32_t afrag[4];
                int r0 = wm + mt * 16 + g;
                afrag[0] = __float_as_uint(as[r0       * AS_STRIDE + kk + tig]);
                afrag[1] = __float_as_uint(as[(r0 + 8) * AS_STRIDE + kk + tig]);
                afrag[2] = __float_as_uint(as[r0       * AS_STRIDE + kk + tig + 4]);
                afrag[3] = __float_as_uint(as[(r0 + 8) * AS_STRIDE + kk + tig + 4]);
                #pragma unroll
                for (int nt = 0; nt < 4; nt++)
                    MMA_TF32(acc[mt][nt], afrag, bfrag[nt]);
            }
        }
    }

    // ----------------------------- epilogue ---------------------------------
    #pragma unroll
    for (int mt = 0; mt < 4; mt++) {
        int r0 = m0 + wm + mt * 16 + g;
        #pragma unroll
        for (int nt = 0; nt < 4; nt++) {
            int cb = n0 + wn + nt * 8 + tig * 2;
            float b0 = bias[cb], b1 = bias[cb + 1];
            #pragma unroll
            for (int half = 0; half < 2; half++) {
                int row = r0 + half * 8;
                float c0 = acc[mt][nt][half * 2 + 0] + b0;
                float c1 = acc[mt][nt][half * 2 + 1] + b1;
                if (mode == 1) {
                    c0 = c0 / (1.0f + expf(-c0));
                    c1 = c1 / (1.0f + expf(-c1));
                    c0 = rna_tf32(c0);          // feeds next GEMM only
                    c1 = rna_tf32(c1);
                } else if (mode == 2) {
                    c0 *= 0.125f; c1 *= 0.125f;
                } else if (mode == 3) {
                    const float2 r = *reinterpret_cast<const float2*>(
                        &res[(size_t)row * N + cb]);
                    c0 += r.x; c1 += r.y;
                } else if (mode == 4) {
                    const float2 r = *reinterpret_cast<const float2*>(
                        &res[(size_t)row * N + cb]);
                    c0 = r.x + 0.5f * c0; c1 = r.y + 0.5f * c1;
                    if (Cr) {
                        float2 rr; rr.x = rna_tf32(c0); rr.y = rna_tf32(c1);
                        *reinterpret_cast<float2*>(&Cr[(size_t)row * N + cb]) = rr;
                    }
                }
                float2 o; o.x = c0; o.y = c1;
                *reinterpret_cast<float2*>(&C[(size_t)row * N + cb]) = o;
            }
        }
    }
}

__global__ __launch_bounds__(256, 2)
void gemm_tc(const float* __restrict__ A, const float* __restrict__ Bm,
             const float* __restrict__ bias, const float* __restrict__ res,
             float* __restrict__ C, float* __restrict__ Cr,
             int N, int K, int mode)
{
    gemm_core(A, Bm, bias, res, C, Cr, N, K, mode);
}

// merged QKV: grid.z selects which projection this CTA computes
__global__ __launch_bounds__(256, 2)
void gemm_qkv(const float* __restrict__ A,
              const float* __restrict__ Bq, const float* __restrict__ Bk,
              const float* __restrict__ Bv,
              const float* __restrict__ bq, const float* __restrict__ bk,
              const float* __restrict__ bv,
              float* __restrict__ Cq, float* __restrict__ Ck,
              float* __restrict__ Cv)
{
    int z = blockIdx.z;
    const float* Bm   = (z == 0) ? Bq : (z == 1) ? Bk : Bv;
    const float* bias = (z == 0) ? bq : (z == 1) ? bk : bv;
    float*       C    = (z == 0) ? Cq : (z == 1) ? Ck : Cv;
    gemm_core(A, Bm, bias, nullptr, C, nullptr, CD, CD, (z == 0) ? 2 : 0);
}

// ------------------------------- Attention ---------------------------------
__global__ void attn_k(const float* __restrict__ q, const float* __restrict__ k,
                       const float* __restrict__ v, const float* __restrict__ hin,
                       float* __restrict__ hout, float* __restrict__ probs)
{
    __shared__ float sc[4][CWB + 1];
    int warp = threadIdx.x >> 5;
    int lane = threadIdx.x & 31;
    int item = blockIdx.x * 4 + warp;          // < B*T*H
    int head = item & (CH - 1);
    int bt   = item >> 3;                      // b*T + t
    int t    = bt & (CT - 1);
    int brow = bt - t;                         // b*T

    const float2* qrow = reinterpret_cast<const float2*>(q + (size_t)bt * CD + head * CDH);
    float2 q2 = qrow[lane];

    for (int w = 0; w < CWB; w++) {
        int tk = t + w - CW1;
        float val = -1e9f;
        if (tk >= 0 && tk < CT) {
            const float2* krow =
                reinterpret_cast<const float2*>(k + (size_t)(brow + tk) * CD + head * CDH);
            float2 k2 = krow[lane];
            float p = q2.x * k2.x + q2.y * k2.y;
            #pragma unroll
            for (int o = 16; o; o >>= 1) p += __shfl_xor_sync(0xffffffffu, p, o);
            val = p;
        }
        if (lane == 0) sc[warp][w] = val;
    }
    __syncwarp();

    float m = -1e30f;
    for (int w = lane; w < CWB; w += 32) m = fmaxf(m, sc[warp][w]);
    #pragma unroll
    for (int o = 16; o; o >>= 1) m = fmaxf(m, __shfl_xor_sync(0xffffffffu, m, o));
    float ssum = 0.0f;
    for (int w = lane; w < CWB; w += 32) {
        float e = expf(sc[warp][w] - m);
        sc[warp][w] = e;
        ssum += e;
    }
    #pragma unroll
    for (int o = 16; o; o >>= 1) ssum += __shfl_xor_sync(0xffffffffu, ssum, o);
    float inv = 1.0f / ssum;
    __syncwarp();

    float* prow = probs + (size_t)item * CWB;
    for (int w = lane; w < CWB; w += 32) {
        float p = sc[warp][w] * inv;
        sc[warp][w] = p;
        prow[w] = p;
    }
    __syncwarp();

    float cx = 0.0f, cy = 0.0f;
    for (int w = 0; w < CWB; w++) {
        int tk = t + w - CW1;
        if (tk < 0 || tk >= CT) continue;
        float p = sc[warp][w];
        const float2* vrow =
            reinterpret_cast<const float2*>(v + (size_t)(brow + tk) * CD + head * CDH);
        float2 v2 = vrow[lane];
        cx = fmaf(p, v2.x, cx);
        cy = fmaf(p, v2.y, cy);
    }
    size_t off = (size_t)bt * CD + head * CDH + lane * 2;
    hout[off]     = hin[off]     + cx;
    hout[off + 1] = hin[off + 1] + cy;
}

// ---------------------------------- GLU ------------------------------------
__global__ void glu_k(const float* __restrict__ in, float* __restrict__ out)
{
    int i = blockIdx.x * 256 + threadIdx.x;    // NTOK*CD threads
    int row = i >> 9;
    int col = i & (CD - 1);
    float a = in[(size_t)row * CCE + col];
    float g = in[(size_t)row * CCE + CD + col];
    out[i] = a / (1.0f + expf(-g));
}

// -------------------- depthwise conv + BN + swish ---------------------------
// output feeds pw2 GEMM only -> store tf32-rounded
__global__ void dwconv_k(const float* __restrict__ in, const float* __restrict__ w,
                         const float* __restrict__ dwb, const float* __restrict__ bng,
                         const float* __restrict__ bnb, float* __restrict__ out)
{
    int c  = blockIdx.y * 128 + threadIdx.x;
    int bt = blockIdx.x;
    int t  = bt & (CT - 1);
    int brow = bt - t;

    float acc = 0.0f;
    #pragma unroll
    for (int kk = 0; kk < CKS; kk++) {
        int tt = t + kk - (CKS - 1) / 2;
        if (tt >= 0 && tt < CT)
            acc = fmaf(__ldg(&w[kk * CD + c]),
                       __ldg(&in[(size_t)(brow + tt) * CD + c]), acc);
    }
    acc += dwb[c];
    acc = acc * (rsqrtf(1.0f + CEPS) * bng[c]) + bnb[c];
    acc = acc / (1.0f + expf(-acc));   // swish
    out[(size_t)bt * CD + c] = rna_tf32(acc);
}

// ------------------------------ launch -------------------------------------
extern "C" void kernel_launch(void* const* d_in, const int* in_sizes, int n_in,
                              void* d_out, int out_size)
{
    (void)in_sizes; (void)n_in; (void)out_size;
    const float* x          = (const float*)d_in[0];
    const float* ff1_ln_g   = (const float*)d_in[1];
    const float* ff1_ln_b   = (const float*)d_in[2];
    const float* ff1_w1     = (const float*)d_in[3];
    const float* ff1_b1     = (const float*)d_in[4];
    const float* ff1_w2     = (const float*)d_in[5];
    const float* ff1_b2     = (const float*)d_in[6];
    const float* ff2_ln_g   = (const float*)d_in[7];
    const float* ff2_ln_b   = (const float*)d_in[8];
    const float* ff2_w1     = (const float*)d_in[9];
    const float* ff2_b1     = (const float*)d_in[10];
    const float* ff2_w2     = (const float*)d_in[11];
    const float* ff2_b2     = (const float*)d_in[12];
    const float* wq         = (const float*)d_in[13];
    const float* bq         = (const float*)d_in[14];
    const float* wk         = (const float*)d_in[15];
    const float* bk         = (const float*)d_in[16];
    const float* wv         = (const float*)d_in[17];
    const float* bv         = (const float*)d_in[18];
    const float* conv_ln_g  = (const float*)d_in[19];
    const float* conv_ln_b  = (const float*)d_in[20];
    const float* conv_pw1_w = (const float*)d_in[21];
    const float* conv_pw1_b = (const float*)d_in[22];
    const float* conv_dw_w  = (const float*)d_in[23];
    const float* conv_dw_b  = (const float*)d_in[24];
    const float* conv_bn_g  = (const float*)d_in[25];
    const float* conv_bn_b  = (const float*)d_in[26];
    const float* conv_pw2_w = (const float*)d_in[27];
    const float* conv_pw2_b = (const float*)d_in[28];
    const float* final_ln_g = (const float*)d_in[29];
    const float* final_ln_b = (const float*)d_in[30];

    float* out_main  = (float*)d_out;                         // (B,T,D)
    float* out_probs = (float*)d_out + (size_t)NTOK * CD;     // (B,T,H,WB)

    float *ln_, *ff_, *h_, *hr_, *h2_, *q_, *k_, *v_, *ce_, *glu_, *dw_;
    cudaGetSymbolAddress((void**)&ln_,  g_ln);
    cudaGetSymbolAddress((void**)&ff_,  g_ff);
    cudaGetSymbolAddress((void**)&h_,   g_h);
    cudaGetSymbolAddress((void**)&hr_,  g_hr);
    cudaGetSymbolAddress((void**)&h2_,  g_h2);
    cudaGetSymbolAddress((void**)&q_,   g_q);
    cudaGetSymbolAddress((void**)&k_,   g_k);
    cudaGetSymbolAddress((void**)&v_,   g_v);
    cudaGetSymbolAddress((void**)&ce_,  g_ce);
    cudaGetSymbolAddress((void**)&glu_, g_glu);
    cudaGetSymbolAddress((void**)&dw_,  g_dw);

    dim3 blk256(256);
    dim3 gFF1(CFF / 128, NTOK / 128);      // 512 CTAs
    dim3 gD  (CD  / 128, NTOK / 128);      // 128 CTAs
    dim3 gCE (CCE / 128, NTOK / 128);      // 256 CTAs
    dim3 gQKV(CD  / 128, NTOK / 128, 3);   // 384 CTAs

    // ---- FF1: h = x + 0.5 * ff(x) ----
    ln_k<true><<<NTOK, 128>>>(x, ff1_ln_g, ff1_ln_b, ln_);
    gemm_tc<<<gFF1, blk256>>>(ln_, ff1_w1, ff1_b1, nullptr, ff_, nullptr, CFF, CD, 1);
    gemm_tc<<<gD,   blk256>>>(ff_, ff1_w2, ff1_b2, x,       h_,  hr_,     CD, CFF, 4);

    // ---- QKV (one launch; A = rounded h) ----
    gemm_qkv<<<gQKV, blk256>>>(hr_, wq, wk, wv, bq, bk, bv, q_, k_, v_);

    // ---- attention (h2 = h + ctx; probs -> d_out) ----
    attn_k<<<(NTOK * CH) / 4, 128>>>(q_, k_, v_, h_, h2_, out_probs);

    // ---- conv module: h = h2 + conv(h2) ----
    ln_k<true><<<NTOK, 128>>>(h2_, conv_ln_g, conv_ln_b, ln_);
    gemm_tc<<<gCE, blk256>>>(ln_, conv_pw1_w, conv_pw1_b, nullptr, ce_, nullptr, CCE, CD, 0);
    glu_k<<<(NTOK * CD) / 256, blk256>>>(ce_, glu_);
    dwconv_k<<<dim3(NTOK, CD / 128), 128>>>(glu_, conv_dw_w, conv_dw_b,
                                            conv_bn_g, conv_bn_b, dw_);
    gemm_tc<<<gD, blk256>>>(dw_, conv_pw2_w, conv_pw2_b, h2_, h_, nullptr, CD, CD, 3);

    // ---- FF2: h2 = h + 0.5 * ff(h) ----
    ln_k<true><<<NTOK, 128>>>(h_, ff2_ln_g, ff2_ln_b, ln_);
    gemm_tc<<<gFF1, blk256>>>(ln_, ff2_w1, ff2_b1, nullptr, ff_, nullptr, CFF, CD, 1);
    gemm_tc<<<gD,   blk256>>>(ff_, ff2_w2, ff2_b2, h_,      h2_, nullptr, CD, CFF, 4);

    // ---- final LN -> out ----
    ln_k<false><<<NTOK, 128>>>(h2_, final_ln_g, final_ln_b, out_main);
}

// round 10
// speedup vs baseline: 1.1159x; 1.1159x over previous
#include <cuda_runtime.h>
#include <math.h>
#include <stdint.h>

// ---------------------------------------------------------------------------
// ConformerBlock: B=4, T=1024, D=512, H=8, DH=64, W1=32, WB=65, FF=2048,
// CE=1024, KS=31. Output = (out[B,T,D], probs[B,T,H,WB]) concatenated fp32.
// GEMMs: tf32 mma.sync, cp.async 3-stage pipeline (wait_group 1), split-K
// for the K=2048 GEMMs. A operands pre-rounded tf32; B converted in-loop.
// ---------------------------------------------------------------------------

#define CB 4
#define CT 1024
#define CD 512
#define CH 8
#define CDH 64
#define CW1 32
#define CWB 65
#define CFF 2048
#define CCE 1024
#define CKS 31
#define CEPS 1e-5f

#define NTOK (CB * CT)          // 4096 rows

// ------------------------- scratch (device globals) ------------------------
__device__ float g_ln [NTOK * CD];
__device__ float g_ff [NTOK * CFF];
__device__ float g_h  [NTOK * CD];
__device__ float g_hr [NTOK * CD];     // rounded copy of h (QKV GEMM A)
__device__ float g_h2 [NTOK * CD];
__device__ float g_q  [NTOK * CD];
__device__ float g_k  [NTOK * CD];
__device__ float g_v  [NTOK * CD];
__device__ float g_ce [NTOK * CCE];
__device__ float g_glu[NTOK * CD];
__device__ float g_dw [NTOK * CD];
__device__ float g_p0 [NTOK * CD];     // split-K partials
__device__ float g_p1 [NTOK * CD];

// ----------------------------- tf32 helpers --------------------------------
__device__ __forceinline__ float rna_tf32(float x)
{
    uint32_t y;
    asm("cvt.rna.tf32.f32 %0, %1;" : "=r"(y) : "f"(x));
    return __uint_as_float(y);
}

__device__ __forceinline__ uint32_t to_tf32(float x)
{
    uint32_t y;
    asm("cvt.rna.tf32.f32 %0, %1;" : "=r"(y) : "f"(x));
    return y;
}

__device__ __forceinline__ void cp16(void* smem_dst, const void* gsrc)
{
    uint32_t s = (uint32_t)__cvta_generic_to_shared(smem_dst);
    asm volatile("cp.async.cg.shared.global [%0], [%1], 16;\n" :: "r"(s), "l"(gsrc));
}

#define MMA_TF32(d, a, b)                                                     \
    asm volatile(                                                             \
        "mma.sync.aligned.m16n8k8.row.col.f32.tf32.tf32.f32 "                 \
        "{%0,%1,%2,%3}, {%4,%5,%6,%7}, {%8,%9}, {%0,%1,%2,%3};"               \
        : "+f"(d[0]), "+f"(d[1]), "+f"(d[2]), "+f"(d[3])                      \
        : "r"(a[0]), "r"(a[1]), "r"(a[2]), "r"(a[3]), "r"(b[0]), "r"(b[1]))

// ------------------------------- LayerNorm ---------------------------------
template<bool ROUND>
__global__ void ln_k(const float* __restrict__ x, const float* __restrict__ g,
                     const float* __restrict__ b, float* __restrict__ y)
{
    int row = blockIdx.x;
    int tid = threadIdx.x;
    const float4* xr = reinterpret_cast<const float4*>(x + (size_t)row * CD);
    float4 v = xr[tid];

    __shared__ float red1[4];
    __shared__ float red2[4];

    float s = v.x + v.y + v.z + v.w;
    #pragma unroll
    for (int o = 16; o; o >>= 1) s += __shfl_xor_sync(0xffffffffu, s, o);
    if ((tid & 31) == 0) red1[tid >> 5] = s;
    __syncthreads();
    float mean = (red1[0] + red1[1] + red1[2] + red1[3]) * (1.0f / CD);

    float dx = v.x - mean, dy = v.y - mean, dz = v.z - mean, dw = v.w - mean;
    float ss = dx * dx + dy * dy + dz * dz + dw * dw;
    #pragma unroll
    for (int o = 16; o; o >>= 1) ss += __shfl_xor_sync(0xffffffffu, ss, o);
    if ((tid & 31) == 0) red2[tid >> 5] = ss;
    __syncthreads();
    float var = (red2[0] + red2[1] + red2[2] + red2[3]) * (1.0f / CD);
    float inv = rsqrtf(var + CEPS);

    float4 gv = reinterpret_cast<const float4*>(g)[tid];
    float4 bv = reinterpret_cast<const float4*>(b)[tid];
    float4 o4;
    o4.x = dx * inv * gv.x + bv.x;
    o4.y = dy * inv * gv.y + bv.y;
    o4.z = dz * inv * gv.z + bv.z;
    o4.w = dw * inv * gv.w + bv.w;
    if (ROUND) {
        o4.x = rna_tf32(o4.x); o4.y = rna_tf32(o4.y);
        o4.z = rna_tf32(o4.z); o4.w = rna_tf32(o4.w);
    }
    reinterpret_cast<float4*>(y + (size_t)row * CD)[tid] = o4;
}

// ------------------------------- TC GEMM core -------------------------------
// C[M=4096, N] = epilogue(A @ B + bias)
// A pre-rounded tf32 in memory; B converted in-loop.
// mode: 0 = bias, 1 = swish (store rounded), 2 = 0.125*(..), 3 = res+,
//       5 = raw accumulator store (split-K partial; bias/res unused)
#define AS_STRIDE 20           // [m][k], pad 16->20
#define BS_STRIDE 136          // [k][n], pad 128->136
#define A_STAGE   (128 * AS_STRIDE)   // 2560 floats
#define B_STAGE   (16 * BS_STRIDE)    // 2176 floats
#define SMEM_BYTES ((3 * (A_STAGE + B_STAGE)) * 4)   // 56832 B

#define GEMM_LOAD_STAGE(sbuf, kbase)                                           \
    {                                                                          \
        float* as_ = sm_a + (sbuf) * A_STAGE;                                  \
        float* bs_ = sm_b + (sbuf) * B_STAGE;                                  \
        _Pragma("unroll")                                                      \
        for (int it = 0; it < 2; it++) {                                       \
            int idx = tid + it * 256;                                          \
            cp16(&as_[(idx >> 2) * AS_STRIDE + (idx & 3) * 4],                 \
                 &A[(size_t)(m0 + (idx >> 2)) * lda + (kbase) + (idx & 3) * 4]);\
            cp16(&bs_[(idx >> 5) * BS_STRIDE + (idx & 31) * 4],                \
                 &Bm[(size_t)((kbase) + (idx >> 5)) * N + n0 + (idx & 31) * 4]);\
        }                                                                      \
        asm volatile("cp.async.commit_group;\n");                              \
    }

__device__ __forceinline__ void gemm_core(
    const float* __restrict__ A, const float* __restrict__ Bm,
    const float* __restrict__ bias, const float* __restrict__ res,
    float* __restrict__ C, int N, int K, int lda, int mode)
{
    extern __shared__ float smem[];
    float* sm_a = smem;                 // 3 stages A
    float* sm_b = smem + 3 * A_STAGE;   // 3 stages B

    const int tid  = threadIdx.x;
    const int lane = tid & 31;
    const int warp = tid >> 5;
    const int g    = lane >> 2;
    const int tig  = lane & 3;

    const int m0 = blockIdx.y * 128;
    const int n0 = blockIdx.x * 128;
    const int wm = (warp & 1) * 64;
    const int wn = (warp >> 1) * 32;

    float acc[4][4][4];
    #pragma unroll
    for (int mt = 0; mt < 4; mt++)
        #pragma unroll
        for (int nt = 0; nt < 4; nt++)
            #pragma unroll
            for (int i = 0; i < 4; i++) acc[mt][nt][i] = 0.0f;

    const int niter = K >> 4;
    GEMM_LOAD_STAGE(0, 0);
    GEMM_LOAD_STAGE(1, 16);

    for (int i = 0; i < niter; i++) {
        asm volatile("cp.async.wait_group 1;\n");
        __syncthreads();
        if (i + 2 < niter) {
            GEMM_LOAD_STAGE((i + 2) % 3, (i + 2) << 4);
        } else {
            asm volatile("cp.async.commit_group;\n");   // keep group count exact
        }

        const float* as = sm_a + (i % 3) * A_STAGE;
        const float* bs = sm_b + (i % 3) * B_STAGE;
        #pragma unroll
        for (int ks = 0; ks < 2; ks++) {
            const int kk = ks * 8;
            uint32_t bfrag[4][2];
            #pragma unroll
            for (int nt = 0; nt < 4; nt++) {
                int col = wn + nt * 8 + g;
                bfrag[nt][0] = to_tf32(bs[(kk + tig)     * BS_STRIDE + col]);
                bfrag[nt][1] = to_tf32(bs[(kk + tig + 4) * BS_STRIDE + col]);
            }
            #pragma unroll
            for (int mt = 0; mt < 4; mt++) {
                uint32_t afrag[4];
                int r0 = wm + mt * 16 + g;
                afrag[0] = __float_as_uint(as[r0       * AS_STRIDE + kk + tig]);
                afrag[1] = __float_as_uint(as[(r0 + 8) * AS_STRIDE + kk + tig]);
                afrag[2] = __float_as_uint(as[r0       * AS_STRIDE + kk + tig + 4]);
                afrag[3] = __float_as_uint(as[(r0 + 8) * AS_STRIDE + kk + tig + 4]);
                #pragma unroll
                for (int nt = 0; nt < 4; nt++)
                    MMA_TF32(acc[mt][nt], afrag, bfrag[nt]);
            }
        }
    }

    // ----------------------------- epilogue ---------------------------------
    #pragma unroll
    for (int mt = 0; mt < 4; mt++) {
        int r0 = m0 + wm + mt * 16 + g;
        #pragma unroll
        for (int nt = 0; nt < 4; nt++) {
            int cb = n0 + wn + nt * 8 + tig * 2;
            if (mode == 5) {    // raw partial store
                #pragma unroll
                for (int half = 0; half < 2; half++) {
                    int row = r0 + half * 8;
                    float2 o;
                    o.x = acc[mt][nt][half * 2 + 0];
                    o.y = acc[mt][nt][half * 2 + 1];
                    *reinterpret_cast<float2*>(&C[(size_t)row * N + cb]) = o;
                }
                continue;
            }
            float b0 = bias[cb], b1 = bias[cb + 1];
            #pragma unroll
            for (int half = 0; half < 2; half++) {
                int row = r0 + half * 8;
                float c0 = acc[mt][nt][half * 2 + 0] + b0;
                float c1 = acc[mt][nt][half * 2 + 1] + b1;
                if (mode == 1) {
                    c0 = c0 / (1.0f + expf(-c0));
                    c1 = c1 / (1.0f + expf(-c1));
                    c0 = rna_tf32(c0);          // feeds next GEMM only
                    c1 = rna_tf32(c1);
                } else if (mode == 2) {
                    c0 *= 0.125f; c1 *= 0.125f;
                } else if (mode == 3) {
                    const float2 r = *reinterpret_cast<const float2*>(
                        &res[(size_t)row * N + cb]);
                    c0 += r.x; c1 += r.y;
                }
                float2 o; o.x = c0; o.y = c1;
                *reinterpret_cast<float2*>(&C[(size_t)row * N + cb]) = o;
            }
        }
    }
}

__global__ __launch_bounds__(256, 2)
void gemm_tc(const float* __restrict__ A, const float* __restrict__ Bm,
             const float* __restrict__ bias, const float* __restrict__ res,
             float* __restrict__ C, int N, int K, int lda, int mode)
{
    gemm_core(A, Bm, bias, res, C, N, K, lda, mode);
}

// split-K=2 over K=2048: z selects K-half; raw partials to p0/p1
__global__ __launch_bounds__(256, 2)
void gemm_splitk(const float* __restrict__ A, const float* __restrict__ Bm,
                 float* __restrict__ p0, float* __restrict__ p1)
{
    int z = blockIdx.z;
    const float* Ah = A + (size_t)z * (CFF / 2);
    const float* Bh = Bm + (size_t)z * (CFF / 2) * CD;
    float* C = z ? p1 : p0;
    gemm_core(Ah, Bh, nullptr, nullptr, C, CD, CFF / 2, CFF, 5);
}

// merged QKV: grid.z selects which projection this CTA computes
__global__ __launch_bounds__(256, 2)
void gemm_qkv(const float* __restrict__ A,
              const float* __restrict__ Bq, const float* __restrict__ Bk,
              const float* __restrict__ Bv,
              const float* __restrict__ bq, const float* __restrict__ bk,
              const float* __restrict__ bv,
              float* __restrict__ Cq, float* __restrict__ Ck,
              float* __restrict__ Cv)
{
    int z = blockIdx.z;
    const float* Bm   = (z == 0) ? Bq : (z == 1) ? Bk : Bv;
    const float* bias = (z == 0) ? bq : (z == 1) ? bk : bv;
    float*       C    = (z == 0) ? Cq : (z == 1) ? Ck : Cv;
    gemm_core(A, Bm, bias, nullptr, C, CD, CD, CD, (z == 0) ? 2 : 0);
}

// split-K combine: C = res + 0.5*(p0 + p1 + bias); Cr = rna(C) if non-null
__global__ void combine_k(const float* __restrict__ p0, const float* __restrict__ p1,
                          const float* __restrict__ bias, const float* __restrict__ res,
                          float* __restrict__ C, float* __restrict__ Cr)
{
    int i = blockIdx.x * 256 + threadIdx.x;       // over NTOK*CD/4
    float4 a0 = reinterpret_cast<const float4*>(p0)[i];
    float4 a1 = reinterpret_cast<const float4*>(p1)[i];
    float4 bv = reinterpret_cast<const float4*>(bias)[i & 127];
    float4 rv = reinterpret_cast<const float4*>(res)[i];
    float4 c;
    c.x = rv.x + 0.5f * (a0.x + a1.x + bv.x);
    c.y = rv.y + 0.5f * (a0.y + a1.y + bv.y);
    c.z = rv.z + 0.5f * (a0.z + a1.z + bv.z);
    c.w = rv.w + 0.5f * (a0.w + a1.w + bv.w);
    reinterpret_cast<float4*>(C)[i] = c;
    if (Cr) {
        float4 r;
        r.x = rna_tf32(c.x); r.y = rna_tf32(c.y);
        r.z = rna_tf32(c.z); r.w = rna_tf32(c.w);
        reinterpret_cast<float4*>(Cr)[i] = r;
    }
}

// ------------------------------- Attention ---------------------------------
__global__ void attn_k(const float* __restrict__ q, const float* __restrict__ k,
                       const float* __restrict__ v, const float* __restrict__ hin,
                       float* __restrict__ hout, float* __restrict__ probs)
{
    __shared__ float sc[4][CWB + 1];
    int warp = threadIdx.x >> 5;
    int lane = threadIdx.x & 31;
    int item = blockIdx.x * 4 + warp;          // < B*T*H
    int head = item & (CH - 1);
    int bt   = item >> 3;                      // b*T + t
    int t    = bt & (CT - 1);
    int brow = bt - t;                         // b*T

    const float2* qrow = reinterpret_cast<const float2*>(q + (size_t)bt * CD + head * CDH);
    float2 q2 = qrow[lane];

    for (int w = 0; w < CWB; w++) {
        int tk = t + w - CW1;
        float val = -1e9f;
        if (tk >= 0 && tk < CT) {
            const float2* krow =
                reinterpret_cast<const float2*>(k + (size_t)(brow + tk) * CD + head * CDH);
            float2 k2 = krow[lane];
            float p = q2.x * k2.x + q2.y * k2.y;
            #pragma unroll
            for (int o = 16; o; o >>= 1) p += __shfl_xor_sync(0xffffffffu, p, o);
            val = p;
        }
        if (lane == 0) sc[warp][w] = val;
    }
    __syncwarp();

    float m = -1e30f;
    for (int w = lane; w < CWB; w += 32) m = fmaxf(m, sc[warp][w]);
    #pragma unroll
    for (int o = 16; o; o >>= 1) m = fmaxf(m, __shfl_xor_sync(0xffffffffu, m, o));
    float ssum = 0.0f;
    for (int w = lane; w < CWB; w += 32) {
        float e = expf(sc[warp][w] - m);
        sc[warp][w] = e;
        ssum += e;
    }
    #pragma unroll
    for (int o = 16; o; o >>= 1) ssum += __shfl_xor_sync(0xffffffffu, ssum, o);
    float inv = 1.0f / ssum;
    __syncwarp();

    float* prow = probs + (size_t)item * CWB;
    for (int w = lane; w < CWB; w += 32) {
        float p = sc[warp][w] * inv;
        sc[warp][w] = p;
        prow[w] = p;
    }
    __syncwarp();

    float cx = 0.0f, cy = 0.0f;
    for (int w = 0; w < CWB; w++) {
        int tk = t + w - CW1;
        if (tk < 0 || tk >= CT) continue;
        float p = sc[warp][w];
        const float2* vrow =
            reinterpret_cast<const float2*>(v + (size_t)(brow + tk) * CD + head * CDH);
        float2 v2 = vrow[lane];
        cx = fmaf(p, v2.x, cx);
        cy = fmaf(p, v2.y, cy);
    }
    size_t off = (size_t)bt * CD + head * CDH + lane * 2;
    hout[off]     = hin[off]     + cx;
    hout[off + 1] = hin[off + 1] + cy;
}

// ---------------------------------- GLU ------------------------------------
__global__ void glu_k(const float* __restrict__ in, float* __restrict__ out)
{
    int i = blockIdx.x * 256 + threadIdx.x;    // NTOK*CD threads
    int row = i >> 9;
    int col = i & (CD - 1);
    float a = in[(size_t)row * CCE + col];
    float g = in[(size_t)row * CCE + CD + col];
    out[i] = a / (1.0f + expf(-g));
}

// -------------------- depthwise conv + BN + swish ---------------------------
__global__ void dwconv_k(const float* __restrict__ in, const float* __restrict__ w,
                         const float* __restrict__ dwb, const float* __restrict__ bng,
                         const float* __restrict__ bnb, float* __restrict__ out)
{
    int c  = blockIdx.y * 128 + threadIdx.x;
    int bt = blockIdx.x;
    int t  = bt & (CT - 1);
    int brow = bt - t;

    float acc = 0.0f;
    #pragma unroll
    for (int kk = 0; kk < CKS; kk++) {
        int tt = t + kk - (CKS - 1) / 2;
        if (tt >= 0 && tt < CT)
            acc = fmaf(__ldg(&w[kk * CD + c]),
                       __ldg(&in[(size_t)(brow + tt) * CD + c]), acc);
    }
    acc += dwb[c];
    acc = acc * (rsqrtf(1.0f + CEPS) * bng[c]) + bnb[c];
    acc = acc / (1.0f + expf(-acc));   // swish
    out[(size_t)bt * CD + c] = rna_tf32(acc);
}

// ------------------------------ launch -------------------------------------
extern "C" void kernel_launch(void* const* d_in, const int* in_sizes, int n_in,
                              void* d_out, int out_size)
{
    (void)in_sizes; (void)n_in; (void)out_size;
    const float* x          = (const float*)d_in[0];
    const float* ff1_ln_g   = (const float*)d_in[1];
    const float* ff1_ln_b   = (const float*)d_in[2];
    const float* ff1_w1     = (const float*)d_in[3];
    const float* ff1_b1     = (const float*)d_in[4];
    const float* ff1_w2     = (const float*)d_in[5];
    const float* ff1_b2     = (const float*)d_in[6];
    const float* ff2_ln_g   = (const float*)d_in[7];
    const float* ff2_ln_b   = (const float*)d_in[8];
    const float* ff2_w1     = (const float*)d_in[9];
    const float* ff2_b1     = (const float*)d_in[10];
    const float* ff2_w2     = (const float*)d_in[11];
    const float* ff2_b2     = (const float*)d_in[12];
    const float* wq         = (const float*)d_in[13];
    const float* bq         = (const float*)d_in[14];
    const float* wk         = (const float*)d_in[15];
    const float* bk         = (const float*)d_in[16];
    const float* wv         = (const float*)d_in[17];
    const float* bv         = (const float*)d_in[18];
    const float* conv_ln_g  = (const float*)d_in[19];
    const float* conv_ln_b  = (const float*)d_in[20];
    const float* conv_pw1_w = (const float*)d_in[21];
    const float* conv_pw1_b = (const float*)d_in[22];
    const float* conv_dw_w  = (const float*)d_in[23];
    const float* conv_dw_b  = (const float*)d_in[24];
    const float* conv_bn_g  = (const float*)d_in[25];
    const float* conv_bn_b  = (const float*)d_in[26];
    const float* conv_pw2_w = (const float*)d_in[27];
    const float* conv_pw2_b = (const float*)d_in[28];
    const float* final_ln_g = (const float*)d_in[29];
    const float* final_ln_b = (const float*)d_in[30];

    float* out_main  = (float*)d_out;                         // (B,T,D)
    float* out_probs = (float*)d_out + (size_t)NTOK * CD;     // (B,T,H,WB)

    float *ln_, *ff_, *h_, *hr_, *h2_, *q_, *k_, *v_, *ce_, *glu_, *dw_, *p0_, *p1_;
    cudaGetSymbolAddress((void**)&ln_,  g_ln);
    cudaGetSymbolAddress((void**)&ff_,  g_ff);
    cudaGetSymbolAddress((void**)&h_,   g_h);
    cudaGetSymbolAddress((void**)&hr_,  g_hr);
    cudaGetSymbolAddress((void**)&h2_,  g_h2);
    cudaGetSymbolAddress((void**)&q_,   g_q);
    cudaGetSymbolAddress((void**)&k_,   g_k);
    cudaGetSymbolAddress((void**)&v_,   g_v);
    cudaGetSymbolAddress((void**)&ce_,  g_ce);
    cudaGetSymbolAddress((void**)&glu_, g_glu);
    cudaGetSymbolAddress((void**)&dw_,  g_dw);
    cudaGetSymbolAddress((void**)&p0_,  g_p0);
    cudaGetSymbolAddress((void**)&p1_,  g_p1);

    cudaFuncSetAttribute(gemm_tc,     cudaFuncAttributeMaxDynamicSharedMemorySize, SMEM_BYTES);
    cudaFuncSetAttribute(gemm_qkv,    cudaFuncAttributeMaxDynamicSharedMemorySize, SMEM_BYTES);
    cudaFuncSetAttribute(gemm_splitk, cudaFuncAttributeMaxDynamicSharedMemorySize, SMEM_BYTES);

    dim3 blk256(256);
    dim3 gFF1(CFF / 128, NTOK / 128);        // 512 CTAs
    dim3 gD  (CD  / 128, NTOK / 128);        // 128 CTAs
    dim3 gCE (CCE / 128, NTOK / 128);        // 256 CTAs
    dim3 gQKV(CD  / 128, NTOK / 128, 3);     // 384 CTAs
    dim3 gDK (CD  / 128, NTOK / 128, 2);     // 256 CTAs (split-K)
    const int nComb = NTOK * CD / 4 / 256;   // 2048 blocks

    // ---- FF1: h = x + 0.5 * ff(x) ----
    ln_k<true><<<NTOK, 128>>>(x, ff1_ln_g, ff1_ln_b, ln_);
    gemm_tc<<<gFF1, blk256, SMEM_BYTES>>>(ln_, ff1_w1, ff1_b1, nullptr, ff_, CFF, CD, CD, 1);
    gemm_splitk<<<gDK, blk256, SMEM_BYTES>>>(ff_, ff1_w2, p0_, p1_);
    combine_k<<<nComb, blk256>>>(p0_, p1_, ff1_b2, x, h_, hr_);

    // ---- QKV (one launch; A = rounded h) ----
    gemm_qkv<<<gQKV, blk256, SMEM_BYTES>>>(hr_, wq, wk, wv, bq, bk, bv, q_, k_, v_);

    // ---- attention (h2 = h + ctx; probs -> d_out) ----
    attn_k<<<(NTOK * CH) / 4, 128>>>(q_, k_, v_, h_, h2_, out_probs);

    // ---- conv module: h = h2 + conv(h2) ----
    ln_k<true><<<NTOK, 128>>>(h2_, conv_ln_g, conv_ln_b, ln_);
    gemm_tc<<<gCE, blk256, SMEM_BYTES>>>(ln_, conv_pw1_w, conv_pw1_b, nullptr, ce_, CCE, CD, CD, 0);
    glu_k<<<(NTOK * CD) / 256, blk256>>>(ce_, glu_);
    dwconv_k<<<dim3(NTOK, CD / 128), 128>>>(glu_, conv_dw_w, conv_dw_b,
                                            conv_bn_g, conv_bn_b, dw_);
    gemm_tc<<<gD, blk256, SMEM_BYTES>>>(dw_, conv_pw2_w, conv_pw2_b, h2_, h_, CD, CD, CD, 3);

    // ---- FF2: h2 = h + 0.5 * ff(h) ----
    ln_k<true><<<NTOK, 128>>>(h_, ff2_ln_g, ff2_ln_b, ln_);
    gemm_tc<<<gFF1, blk256, SMEM_BYTES>>>(ln_, ff2_w1, ff2_b1, nullptr, ff_, CFF, CD, CD, 1);
    gemm_splitk<<<gDK, blk256, SMEM_BYTES>>>(ff_, ff2_w2, p0_, p1_);
    combine_k<<<nComb, blk256>>>(p0_, p1_, ff2_b2, h_, h2_, nullptr);

    // ---- final LN -> out ----
    ln_k<false><<<NTOK, 128>>>(h2_, final_ln_g, final_ln_b, out_main);
}

// round 11
// speedup vs baseline: 1.1412x; 1.0226x over previous
#include <cuda_runtime.h>
#include <math.h>
#include <stdint.h>

// ---------------------------------------------------------------------------
// ConformerBlock: B=4, T=1024, D=512, H=8, DH=64, W1=32, WB=65, FF=2048,
// CE=1024, KS=31. Output = (out[B,T,D], probs[B,T,H,WB]) concatenated fp32.
// GEMMs: tf32 mma.sync, cp.async 3-stage pipeline (wait_group 1), split-K for
// K=2048 FF-w2 GEMMs and the pw2 GEMM. A operands pre-rounded tf32 at
// producers; B (weights) converted in-loop. FF2 combine fused with final LN.
// ---------------------------------------------------------------------------

#define CB 4
#define CT 1024
#define CD 512
#define CH 8
#define CDH 64
#define CW1 32
#define CWB 65
#define CFF 2048
#define CCE 1024
#define CKS 31
#define CEPS 1e-5f

#define NTOK (CB * CT)          // 4096 rows

// ------------------------- scratch (device globals) ------------------------
__device__ float g_ln [NTOK * CD];
__device__ float g_ff [NTOK * CFF];
__device__ float g_h  [NTOK * CD];
__device__ float g_hr [NTOK * CD];     // rounded copy of h (QKV GEMM A)
__device__ float g_h2 [NTOK * CD];
__device__ float g_q  [NTOK * CD];
__device__ float g_k  [NTOK * CD];
__device__ float g_v  [NTOK * CD];
__device__ float g_ce [NTOK * CCE];
__device__ float g_glu[NTOK * CD];
__device__ float g_dw [NTOK * CD];
__device__ float g_p0 [NTOK * CD];     // split-K partials
__device__ float g_p1 [NTOK * CD];

// ----------------------------- helpers -------------------------------------
__device__ __forceinline__ float rna_tf32(float x)
{
    uint32_t y;
    asm("cvt.rna.tf32.f32 %0, %1;" : "=r"(y) : "f"(x));
    return __uint_as_float(y);
}

__device__ __forceinline__ uint32_t to_tf32(float x)
{
    uint32_t y;
    asm("cvt.rna.tf32.f32 %0, %1;" : "=r"(y) : "f"(x));
    return y;
}

__device__ __forceinline__ float fsig(float x)   // fast sigmoid
{
    return 1.0f / (1.0f + __expf(-x));
}

__device__ __forceinline__ void cp16(void* smem_dst, const void* gsrc)
{
    uint32_t s = (uint32_t)__cvta_generic_to_shared(smem_dst);
    asm volatile("cp.async.cg.shared.global [%0], [%1], 16;\n" :: "r"(s), "l"(gsrc));
}

#define MMA_TF32(d, a, b)                                                     \
    asm volatile(                                                             \
        "mma.sync.aligned.m16n8k8.row.col.f32.tf32.tf32.f32 "                 \
        "{%0,%1,%2,%3}, {%4,%5,%6,%7}, {%8,%9}, {%0,%1,%2,%3};"               \
        : "+f"(d[0]), "+f"(d[1]), "+f"(d[2]), "+f"(d[3])                      \
        : "r"(a[0]), "r"(a[1]), "r"(a[2]), "r"(a[3]), "r"(b[0]), "r"(b[1]))

// ------------------------------- LayerNorm ---------------------------------
template<bool ROUND>
__global__ void ln_k(const float* __restrict__ x, const float* __restrict__ g,
                     const float* __restrict__ b, float* __restrict__ y)
{
    int row = blockIdx.x;
    int tid = threadIdx.x;
    const float4* xr = reinterpret_cast<const float4*>(x + (size_t)row * CD);
    float4 v = xr[tid];

    __shared__ float red1[4];
    __shared__ float red2[4];

    float s = v.x + v.y + v.z + v.w;
    #pragma unroll
    for (int o = 16; o; o >>= 1) s += __shfl_xor_sync(0xffffffffu, s, o);
    if ((tid & 31) == 0) red1[tid >> 5] = s;
    __syncthreads();
    float mean = (red1[0] + red1[1] + red1[2] + red1[3]) * (1.0f / CD);

    float dx = v.x - mean, dy = v.y - mean, dz = v.z - mean, dw = v.w - mean;
    float ss = dx * dx + dy * dy + dz * dz + dw * dw;
    #pragma unroll
    for (int o = 16; o; o >>= 1) ss += __shfl_xor_sync(0xffffffffu, ss, o);
    if ((tid & 31) == 0) red2[tid >> 5] = ss;
    __syncthreads();
    float var = (red2[0] + red2[1] + red2[2] + red2[3]) * (1.0f / CD);
    float inv = rsqrtf(var + CEPS);

    float4 gv = reinterpret_cast<const float4*>(g)[tid];
    float4 bv = reinterpret_cast<const float4*>(b)[tid];
    float4 o4;
    o4.x = dx * inv * gv.x + bv.x;
    o4.y = dy * inv * gv.y + bv.y;
    o4.z = dz * inv * gv.z + bv.z;
    o4.w = dw * inv * gv.w + bv.w;
    if (ROUND) {
        o4.x = rna_tf32(o4.x); o4.y = rna_tf32(o4.y);
        o4.z = rna_tf32(o4.z); o4.w = rna_tf32(o4.w);
    }
    reinterpret_cast<float4*>(y + (size_t)row * CD)[tid] = o4;
}

// ------------------------------- TC GEMM core -------------------------------
// C[M=4096, N] = epilogue(A @ B + bias)
// A pre-rounded tf32 in memory; B converted in-loop.
// mode: 0 = bias, 1 = swish (store rounded), 2 = 0.125*(..), 3 = res+,
//       5 = raw accumulator store (split-K partial; bias/res unused)
#define AS_STRIDE 20           // [m][k], pad 16->20
#define BS_STRIDE 136          // [k][n], pad 128->136
#define A_STAGE   (128 * AS_STRIDE)   // 2560 floats
#define B_STAGE   (16 * BS_STRIDE)    // 2176 floats
#define SMEM_BYTES ((3 * (A_STAGE + B_STAGE)) * 4)   // 56832 B

#define GEMM_LOAD_STAGE(sbuf, kbase)                                           \
    {                                                                          \
        float* as_ = sm_a + (sbuf) * A_STAGE;                                  \
        float* bs_ = sm_b + (sbuf) * B_STAGE;                                  \
        _Pragma("unroll")                                                      \
        for (int it = 0; it < 2; it++) {                                       \
            int idx = tid + it * 256;                                          \
            cp16(&as_[(idx >> 2) * AS_STRIDE + (idx & 3) * 4],                 \
                 &A[(size_t)(m0 + (idx >> 2)) * lda + (kbase) + (idx & 3) * 4]);\
            cp16(&bs_[(idx >> 5) * BS_STRIDE + (idx & 31) * 4],                \
                 &Bm[(size_t)((kbase) + (idx >> 5)) * N + n0 + (idx & 31) * 4]);\
        }                                                                      \
        asm volatile("cp.async.commit_group;\n");                              \
    }

__device__ __forceinline__ void gemm_core(
    const float* __restrict__ A, const float* __restrict__ Bm,
    const float* __restrict__ bias, const float* __restrict__ res,
    float* __restrict__ C, int N, int K, int lda, int mode)
{
    extern __shared__ float smem[];
    float* sm_a = smem;                 // 3 stages A
    float* sm_b = smem + 3 * A_STAGE;   // 3 stages B

    const int tid  = threadIdx.x;
    const int lane = tid & 31;
    const int warp = tid >> 5;
    const int g    = lane >> 2;
    const int tig  = lane & 3;

    const int m0 = blockIdx.y * 128;
    const int n0 = blockIdx.x * 128;
    const int wm = (warp & 1) * 64;
    const int wn = (warp >> 1) * 32;

    float acc[4][4][4];
    #pragma unroll
    for (int mt = 0; mt < 4; mt++)
        #pragma unroll
        for (int nt = 0; nt < 4; nt++)
            #pragma unroll
            for (int i = 0; i < 4; i++) acc[mt][nt][i] = 0.0f;

    const int niter = K >> 4;
    GEMM_LOAD_STAGE(0, 0);
    GEMM_LOAD_STAGE(1, 16);

    for (int i = 0; i < niter; i++) {
        asm volatile("cp.async.wait_group 1;\n");
        __syncthreads();
        if (i + 2 < niter) {
            GEMM_LOAD_STAGE((i + 2) % 3, (i + 2) << 4);
        } else {
            asm volatile("cp.async.commit_group;\n");   // keep group count exact
        }

        const float* as = sm_a + (i % 3) * A_STAGE;
        const float* bs = sm_b + (i % 3) * B_STAGE;
        #pragma unroll
        for (int ks = 0; ks < 2; ks++) {
            const int kk = ks * 8;
            uint32_t bfrag[4][2];
            #pragma unroll
            for (int nt = 0; nt < 4; nt++) {
                int col = wn + nt * 8 + g;
                bfrag[nt][0] = to_tf32(bs[(kk + tig)     * BS_STRIDE + col]);
                bfrag[nt][1] = to_tf32(bs[(kk + tig + 4) * BS_STRIDE + col]);
            }
            #pragma unroll
            for (int mt = 0; mt < 4; mt++) {
                uint32_t afrag[4];
                int r0 = wm + mt * 16 + g;
                afrag[0] = __float_as_uint(as[r0       * AS_STRIDE + kk + tig]);
                afrag[1] = __float_as_uint(as[(r0 + 8) * AS_STRIDE + kk + tig]);
                afrag[2] = __float_as_uint(as[r0       * AS_STRIDE + kk + tig + 4]);
                afrag[3] = __float_as_uint(as[(r0 + 8) * AS_STRIDE + kk + tig + 4]);
                #pragma unroll
                for (int nt = 0; nt < 4; nt++)
                    MMA_TF32(acc[mt][nt], afrag, bfrag[nt]);
            }
        }
    }

    // ----------------------------- epilogue ---------------------------------
    #pragma unroll
    for (int mt = 0; mt < 4; mt++) {
        int r0 = m0 + wm + mt * 16 + g;
        #pragma unroll
        for (int nt = 0; nt < 4; nt++) {
            int cb = n0 + wn + nt * 8 + tig * 2;
            if (mode == 5) {    // raw partial store
                #pragma unroll
                for (int half = 0; half < 2; half++) {
                    int row = r0 + half * 8;
                    float2 o;
                    o.x = acc[mt][nt][half * 2 + 0];
                    o.y = acc[mt][nt][half * 2 + 1];
                    *reinterpret_cast<float2*>(&C[(size_t)row * N + cb]) = o;
                }
                continue;
            }
            float b0 = bias[cb], b1 = bias[cb + 1];
            #pragma unroll
            for (int half = 0; half < 2; half++) {
                int row = r0 + half * 8;
                float c0 = acc[mt][nt][half * 2 + 0] + b0;
                float c1 = acc[mt][nt][half * 2 + 1] + b1;
                if (mode == 1) {
                    c0 *= fsig(c0);
                    c1 *= fsig(c1);
                    c0 = rna_tf32(c0);          // feeds next GEMM only
                    c1 = rna_tf32(c1);
                } else if (mode == 2) {
                    c0 *= 0.125f; c1 *= 0.125f;
                } else if (mode == 3) {
                    const float2 r = *reinterpret_cast<const float2*>(
                        &res[(size_t)row * N + cb]);
                    c0 += r.x; c1 += r.y;
                }
                float2 o; o.x = c0; o.y = c1;
                *reinterpret_cast<float2*>(&C[(size_t)row * N + cb]) = o;
            }
        }
    }
}

__global__ __launch_bounds__(256, 2)
void gemm_tc(const float* __restrict__ A, const float* __restrict__ Bm,
             const float* __restrict__ bias, const float* __restrict__ res,
             float* __restrict__ C, int N, int K, int lda, int mode)
{
    gemm_core(A, Bm, bias, res, C, N, K, lda, mode);
}

// split-K=2 over K (any even K): z selects K-half; raw partials to p0/p1
__global__ __launch_bounds__(256, 2)
void gemm_splitk(const float* __restrict__ A, const float* __restrict__ Bm,
                 float* __restrict__ p0, float* __restrict__ p1,
                 int K, int lda)
{
    int z = blockIdx.z;
    int Kh = K >> 1;
    const float* Ah = A + (size_t)z * Kh;
    const float* Bh = Bm + (size_t)z * Kh * CD;
    float* C = z ? p1 : p0;
    gemm_core(Ah, Bh, nullptr, nullptr, C, CD, Kh, lda, 5);
}

// merged QKV: grid.z selects which projection this CTA computes
__global__ __launch_bounds__(256, 2)
void gemm_qkv(const float* __restrict__ A,
              const float* __restrict__ Bq, const float* __restrict__ Bk,
              const float* __restrict__ Bv,
              const float* __restrict__ bq, const float* __restrict__ bk,
              const float* __restrict__ bv,
              float* __restrict__ Cq, float* __restrict__ Ck,
              float* __restrict__ Cv)
{
    int z = blockIdx.z;
    const float* Bm   = (z == 0) ? Bq : (z == 1) ? Bk : Bv;
    const float* bias = (z == 0) ? bq : (z == 1) ? bk : bv;
    float*       C    = (z == 0) ? Cq : (z == 1) ? Ck : Cv;
    gemm_core(A, Bm, bias, nullptr, C, CD, CD, CD, (z == 0) ? 2 : 0);
}

// split-K combine: C = res + scale*(p0 + p1 + bias); Cr = rna(C) if non-null
__global__ void combine_k(const float* __restrict__ p0, const float* __restrict__ p1,
                          const float* __restrict__ bias, const float* __restrict__ res,
                          float* __restrict__ C, float* __restrict__ Cr, float scale)
{
    int i = blockIdx.x * 256 + threadIdx.x;       // over NTOK*CD/4
    float4 a0 = reinterpret_cast<const float4*>(p0)[i];
    float4 a1 = reinterpret_cast<const float4*>(p1)[i];
    float4 bv = reinterpret_cast<const float4*>(bias)[i & 127];
    float4 rv = reinterpret_cast<const float4*>(res)[i];
    float4 c;
    c.x = rv.x + scale * (a0.x + a1.x + bv.x);
    c.y = rv.y + scale * (a0.y + a1.y + bv.y);
    c.z = rv.z + scale * (a0.z + a1.z + bv.z);
    c.w = rv.w + scale * (a0.w + a1.w + bv.w);
    reinterpret_cast<float4*>(C)[i] = c;
    if (Cr) {
        float4 r;
        r.x = rna_tf32(c.x); r.y = rna_tf32(c.y);
        r.z = rna_tf32(c.z); r.w = rna_tf32(c.w);
        reinterpret_cast<float4*>(Cr)[i] = r;
    }
}

// fused FF2-combine + final LN: h2 = res + 0.5*(p0+p1+bias); out = LN(h2)
__global__ void combine_ln_k(const float* __restrict__ p0, const float* __restrict__ p1,
                             const float* __restrict__ bias, const float* __restrict__ res,
                             const float* __restrict__ lng, const float* __restrict__ lnb,
                             float* __restrict__ out)
{
    int row = blockIdx.x;
    int tid = threadIdx.x;
    size_t base = (size_t)row * CD;

    float4 a0 = reinterpret_cast<const float4*>(p0 + base)[tid];
    float4 a1 = reinterpret_cast<const float4*>(p1 + base)[tid];
    float4 bv = reinterpret_cast<const float4*>(bias)[tid];
    float4 rv = reinterpret_cast<const float4*>(res + base)[tid];
    float4 v;
    v.x = rv.x + 0.5f * (a0.x + a1.x + bv.x);
    v.y = rv.y + 0.5f * (a0.y + a1.y + bv.y);
    v.z = rv.z + 0.5f * (a0.z + a1.z + bv.z);
    v.w = rv.w + 0.5f * (a0.w + a1.w + bv.w);

    __shared__ float red1[4];
    __shared__ float red2[4];

    float s = v.x + v.y + v.z + v.w;
    #pragma unroll
    for (int o = 16; o; o >>= 1) s += __shfl_xor_sync(0xffffffffu, s, o);
    if ((tid & 31) == 0) red1[tid >> 5] = s;
    __syncthreads();
    float mean = (red1[0] + red1[1] + red1[2] + red1[3]) * (1.0f / CD);

    float dx = v.x - mean, dy = v.y - mean, dz = v.z - mean, dw = v.w - mean;
    float ss = dx * dx + dy * dy + dz * dz + dw * dw;
    #pragma unroll
    for (int o = 16; o; o >>= 1) ss += __shfl_xor_sync(0xffffffffu, ss, o);
    if ((tid & 31) == 0) red2[tid >> 5] = ss;
    __syncthreads();
    float var = (red2[0] + red2[1] + red2[2] + red2[3]) * (1.0f / CD);
    float inv = rsqrtf(var + CEPS);

    float4 gv = reinterpret_cast<const float4*>(lng)[tid];
    float4 lb = reinterpret_cast<const float4*>(lnb)[tid];
    float4 o4;
    o4.x = dx * inv * gv.x + lb.x;
    o4.y = dy * inv * gv.y + lb.y;
    o4.z = dz * inv * gv.z + lb.z;
    o4.w = dw * inv * gv.w + lb.w;
    reinterpret_cast<float4*>(out + base)[tid] = o4;
}

// ------------------------------- Attention ---------------------------------
__global__ void attn_k(const float* __restrict__ q, const float* __restrict__ k,
                       const float* __restrict__ v, const float* __restrict__ hin,
                       float* __restrict__ hout, float* __restrict__ probs)
{
    __shared__ float sc[4][CWB + 1];
    int warp = threadIdx.x >> 5;
    int lane = threadIdx.x & 31;
    int item = blockIdx.x * 4 + warp;          // < B*T*H
    int head = item & (CH - 1);
    int bt   = item >> 3;                      // b*T + t
    int t    = bt & (CT - 1);
    int brow = bt - t;                         // b*T

    const float2* qrow = reinterpret_cast<const float2*>(q + (size_t)bt * CD + head * CDH);
    float2 q2 = qrow[lane];

    for (int w = 0; w < CWB; w++) {
        int tk = t + w - CW1;
        float val = -1e9f;
        if (tk >= 0 && tk < CT) {
            const float2* krow =
                reinterpret_cast<const float2*>(k + (size_t)(brow + tk) * CD + head * CDH);
            float2 k2 = krow[lane];
            float p = q2.x * k2.x + q2.y * k2.y;
            #pragma unroll
            for (int o = 16; o; o >>= 1) p += __shfl_xor_sync(0xffffffffu, p, o);
            val = p;
        }
        if (lane == 0) sc[warp][w] = val;
    }
    __syncwarp();

    float m = -1e30f;
    for (int w = lane; w < CWB; w += 32) m = fmaxf(m, sc[warp][w]);
    #pragma unroll
    for (int o = 16; o; o >>= 1) m = fmaxf(m, __shfl_xor_sync(0xffffffffu, m, o));
    float ssum = 0.0f;
    for (int w = lane; w < CWB; w += 32) {
        float e = expf(sc[warp][w] - m);
        sc[warp][w] = e;
        ssum += e;
    }
    #pragma unroll
    for (int o = 16; o; o >>= 1) ssum += __shfl_xor_sync(0xffffffffu, ssum, o);
    float inv = 1.0f / ssum;
    __syncwarp();

    float* prow = probs + (size_t)item * CWB;
    for (int w = lane; w < CWB; w += 32) {
        float p = sc[warp][w] * inv;
        sc[warp][w] = p;
        prow[w] = p;
    }
    __syncwarp();

    float cx = 0.0f, cy = 0.0f;
    for (int w = 0; w < CWB; w++) {
        int tk = t + w - CW1;
        if (tk < 0 || tk >= CT) continue;
        float p = sc[warp][w];
        const float2* vrow =
            reinterpret_cast<const float2*>(v + (size_t)(brow + tk) * CD + head * CDH);
        float2 v2 = vrow[lane];
        cx = fmaf(p, v2.x, cx);
        cy = fmaf(p, v2.y, cy);
    }
    size_t off = (size_t)bt * CD + head * CDH + lane * 2;
    hout[off]     = hin[off]     + cx;
    hout[off + 1] = hin[off + 1] + cy;
}

// ---------------------------------- GLU ------------------------------------
__global__ void glu_k(const float* __restrict__ in, float* __restrict__ out)
{
    int i = blockIdx.x * 256 + threadIdx.x;    // NTOK*CD threads
    int row = i >> 9;
    int col = i & (CD - 1);
    float a = in[(size_t)row * CCE + col];
    float g = in[(size_t)row * CCE + CD + col];
    out[i] = a * fsig(g);
}

// -------------------- depthwise conv + BN + swish ---------------------------
__global__ void dwconv_k(const float* __restrict__ in, const float* __restrict__ w,
                         const float* __restrict__ dwb, const float* __restrict__ bng,
                         const float* __restrict__ bnb, float* __restrict__ out)
{
    int c  = blockIdx.y * 128 + threadIdx.x;
    int bt = blockIdx.x;
    int t  = bt & (CT - 1);
    int brow = bt - t;

    float acc = 0.0f;
    #pragma unroll
    for (int kk = 0; kk < CKS; kk++) {
        int tt = t + kk - (CKS - 1) / 2;
        if (tt >= 0 && tt < CT)
            acc = fmaf(__ldg(&w[kk * CD + c]),
                       __ldg(&in[(size_t)(brow + tt) * CD + c]), acc);
    }
    acc += dwb[c];
    acc = acc * (rsqrtf(1.0f + CEPS) * bng[c]) + bnb[c];
    acc = acc * fsig(acc);             // swish
    out[(size_t)bt * CD + c] = rna_tf32(acc);
}

// ------------------------------ launch -------------------------------------
extern "C" void kernel_launch(void* const* d_in, const int* in_sizes, int n_in,
                              void* d_out, int out_size)
{
    (void)in_sizes; (void)n_in; (void)out_size;
    const float* x          = (const float*)d_in[0];
    const float* ff1_ln_g   = (const float*)d_in[1];
    const float* ff1_ln_b   = (const float*)d_in[2];
    const float* ff1_w1     = (const float*)d_in[3];
    const float* ff1_b1     = (const float*)d_in[4];
    const float* ff1_w2     = (const float*)d_in[5];
    const float* ff1_b2     = (const float*)d_in[6];
    const float* ff2_ln_g   = (const float*)d_in[7];
    const float* ff2_ln_b   = (const float*)d_in[8];
    const float* ff2_w1     = (const float*)d_in[9];
    const float* ff2_b1     = (const float*)d_in[10];
    const float* ff2_w2     = (const float*)d_in[11];
    const float* ff2_b2     = (const float*)d_in[12];
    const float* wq         = (const float*)d_in[13];
    const float* bq         = (const float*)d_in[14];
    const float* wk         = (const float*)d_in[15];
    const float* bk         = (const float*)d_in[16];
    const float* wv         = (const float*)d_in[17];
    const float* bv         = (const float*)d_in[18];
    const float* conv_ln_g  = (const float*)d_in[19];
    const float* conv_ln_b  = (const float*)d_in[20];
    const float* conv_pw1_w = (const float*)d_in[21];
    const float* conv_pw1_b = (const float*)d_in[22];
    const float* conv_dw_w  = (const float*)d_in[23];
    const float* conv_dw_b  = (const float*)d_in[24];
    const float* conv_bn_g  = (const float*)d_in[25];
    const float* conv_bn_b  = (const float*)d_in[26];
    const float* conv_pw2_w = (const float*)d_in[27];
    const float* conv_pw2_b = (const float*)d_in[28];
    const float* final_ln_g = (const float*)d_in[29];
    const float* final_ln_b = (const float*)d_in[30];

    float* out_main  = (float*)d_out;                         // (B,T,D)
    float* out_probs = (float*)d_out + (size_t)NTOK * CD;     // (B,T,H,WB)

    float *ln_, *ff_, *h_, *hr_, *h2_, *q_, *k_, *v_, *ce_, *glu_, *dw_, *p0_, *p1_;
    cudaGetSymbolAddress((void**)&ln_,  g_ln);
    cudaGetSymbolAddress((void**)&ff_,  g_ff);
    cudaGetSymbolAddress((void**)&h_,   g_h);
    cudaGetSymbolAddress((void**)&hr_,  g_hr);
    cudaGetSymbolAddress((void**)&h2_,  g_h2);
    cudaGetSymbolAddress((void**)&q_,   g_q);
    cudaGetSymbolAddress((void**)&k_,   g_k);
    cudaGetSymbolAddress((void**)&v_,   g_v);
    cudaGetSymbolAddress((void**)&ce_,  g_ce);
    cudaGetSymbolAddress((void**)&glu_, g_glu);
    cudaGetSymbolAddress((void**)&dw_,  g_dw);
    cudaGetSymbolAddress((void**)&p0_,  g_p0);
    cudaGetSymbolAddress((void**)&p1_,  g_p1);

    cudaFuncSetAttribute(gemm_tc,     cudaFuncAttributeMaxDynamicSharedMemorySize, SMEM_BYTES);
    cudaFuncSetAttribute(gemm_qkv,    cudaFuncAttributeMaxDynamicSharedMemorySize, SMEM_BYTES);
    cudaFuncSetAttribute(gemm_splitk, cudaFuncAttributeMaxDynamicSharedMemorySize, SMEM_BYTES);

    dim3 blk256(256);
    dim3 gFF1(CFF / 128, NTOK / 128);        // 512 CTAs
    dim3 gCE (CCE / 128, NTOK / 128);        // 256 CTAs
    dim3 gQKV(CD  / 128, NTOK / 128, 3);     // 384 CTAs
    dim3 gDK (CD  / 128, NTOK / 128, 2);     // 256 CTAs (split-K)
    const int nComb = NTOK * CD / 4 / 256;   // 2048 blocks

    // ---- FF1: h = x + 0.5 * ff(x) ----
    ln_k<true><<<NTOK, 128>>>(x, ff1_ln_g, ff1_ln_b, ln_);
    gemm_tc<<<gFF1, blk256, SMEM_BYTES>>>(ln_, ff1_w1, ff1_b1, nullptr, ff_, CFF, CD, CD, 1);
    gemm_splitk<<<gDK, blk256, SMEM_BYTES>>>(ff_, ff1_w2, p0_, p1_, CFF, CFF);
    combine_k<<<nComb, blk256>>>(p0_, p1_, ff1_b2, x, h_, hr_, 0.5f);

    // ---- QKV (one launch; A = rounded h) ----
    gemm_qkv<<<gQKV, blk256, SMEM_BYTES>>>(hr_, wq, wk, wv, bq, bk, bv, q_, k_, v_);

    // ---- attention (h2 = h + ctx; probs -> d_out) ----
    attn_k<<<(NTOK * CH) / 4, 128>>>(q_, k_, v_, h_, h2_, out_probs);

    // ---- conv module: h = h2 + conv(h2) ----
    ln_k<true><<<NTOK, 128>>>(h2_, conv_ln_g, conv_ln_b, ln_);
    gemm_tc<<<gCE, blk256, SMEM_BYTES>>>(ln_, conv_pw1_w, conv_pw1_b, nullptr, ce_, CCE, CD, CD, 0);
    glu_k<<<(NTOK * CD) / 256, blk256>>>(ce_, glu_);
    dwconv_k<<<dim3(NTOK, CD / 128), 128>>>(glu_, conv_dw_w, conv_dw_b,
                                            conv_bn_g, conv_bn_b, dw_);
    gemm_splitk<<<gDK, blk256, SMEM_BYTES>>>(dw_, conv_pw2_w, p0_, p1_, CD, CD);
    combine_k<<<nComb, blk256>>>(p0_, p1_, conv_pw2_b, h2_, h_, nullptr, 1.0f);

    // ---- FF2: h2 = h + 0.5 * ff(h); out = LN(h2) ----
    ln_k<true><<<NTOK, 128>>>(h_, ff2_ln_g, ff2_ln_b, ln_);
    gemm_tc<<<gFF1, blk256, SMEM_BYTES>>>(ln_, ff2_w1, ff2_b1, nullptr, ff_, CFF, CD, CD, 1);
    gemm_splitk<<<gDK, blk256, SMEM_BYTES>>>(ff_, ff2_w2, p0_, p1_, CFF, CFF);
    combine_ln_k<<<NTOK, 128>>>(p0_, p1_, ff2_b2, h_, final_ln_g, final_ln_b, out_main);
}

// round 13
// speedup vs baseline: 1.1782x; 1.0324x over previous
#include <cuda_runtime.h>
#include <math.h>
#include <stdint.h>

// ---------------------------------------------------------------------------
// ConformerBlock: B=4, T=1024, D=512, H=8, DH=64, W1=32, WB=65, FF=2048,
// CE=1024, KS=31. Output = (out[B,T,D], probs[B,T,H,WB]) concatenated fp32.
// GEMMs: tf32 mma.sync, BK=32 2-stage cp.async pipeline, split-K for the
// K=2048 FF-w2 GEMMs and the pw2 GEMM. A operands pre-rounded tf32 at
// producers; B (weights) converted in-loop. FF2 combine fused with final LN.
// ---------------------------------------------------------------------------

#define CB 4
#define CT 1024
#define CD 512
#define CH 8
#define CDH 64
#define CW1 32
#define CWB 65
#define CFF 2048
#define CCE 1024
#define CKS 31
#define CEPS 1e-5f

#define NTOK (CB * CT)          // 4096 rows

// ------------------------- scratch (device globals) ------------------------
__device__ float g_ln [NTOK * CD];
__device__ float g_ff [NTOK * CFF];
__device__ float g_h  [NTOK * CD];
__device__ float g_hr [NTOK * CD];     // rounded copy of h (QKV GEMM A)
__device__ float g_h2 [NTOK * CD];
__device__ float g_q  [NTOK * CD];
__device__ float g_k  [NTOK * CD];
__device__ float g_v  [NTOK * CD];
__device__ float g_ce [NTOK * CCE];
__device__ float g_glu[NTOK * CD];
__device__ float g_dw [NTOK * CD];
__device__ float g_p0 [NTOK * CD];     // split-K partials
__device__ float g_p1 [NTOK * CD];

// ----------------------------- helpers -------------------------------------
__device__ __forceinline__ float rna_tf32(float x)
{
    uint32_t y;
    asm("cvt.rna.tf32.f32 %0, %1;" : "=r"(y) : "f"(x));
    return __uint_as_float(y);
}

__device__ __forceinline__ uint32_t to_tf32(float x)
{
    uint32_t y;
    asm("cvt.rna.tf32.f32 %0, %1;" : "=r"(y) : "f"(x));
    return y;
}

__device__ __forceinline__ float fsig(float x)   // fast sigmoid
{
    return 1.0f / (1.0f + __expf(-x));
}

__device__ __forceinline__ void cp16(void* smem_dst, const void* gsrc)
{
    uint32_t s = (uint32_t)__cvta_generic_to_shared(smem_dst);
    asm volatile("cp.async.cg.shared.global [%0], [%1], 16;\n" :: "r"(s), "l"(gsrc));
}

#define MMA_TF32(d, a, b)                                                     \
    asm volatile(                                                             \
        "mma.sync.aligned.m16n8k8.row.col.f32.tf32.tf32.f32 "                 \
        "{%0,%1,%2,%3}, {%4,%5,%6,%7}, {%8,%9}, {%0,%1,%2,%3};"               \
        : "+f"(d[0]), "+f"(d[1]), "+f"(d[2]), "+f"(d[3])                      \
        : "r"(a[0]), "r"(a[1]), "r"(a[2]), "r"(a[3]), "r"(b[0]), "r"(b[1]))

// ------------------------------- LayerNorm ---------------------------------
template<bool ROUND>
__global__ void ln_k(const float* __restrict__ x, const float* __restrict__ g,
                     const float* __restrict__ b, float* __restrict__ y)
{
    int row = blockIdx.x;
    int tid = threadIdx.x;
    const float4* xr = reinterpret_cast<const float4*>(x + (size_t)row * CD);
    float4 v = xr[tid];

    __shared__ float red1[4];
    __shared__ float red2[4];

    float s = v.x + v.y + v.z + v.w;
    #pragma unroll
    for (int o = 16; o; o >>= 1) s += __shfl_xor_sync(0xffffffffu, s, o);
    if ((tid & 31) == 0) red1[tid >> 5] = s;
    __syncthreads();
    float mean = (red1[0] + red1[1] + red1[2] + red1[3]) * (1.0f / CD);

    float dx = v.x - mean, dy = v.y - mean, dz = v.z - mean, dw = v.w - mean;
    float ss = dx * dx + dy * dy + dz * dz + dw * dw;
    #pragma unroll
    for (int o = 16; o; o >>= 1) ss += __shfl_xor_sync(0xffffffffu, ss, o);
    if ((tid & 31) == 0) red2[tid >> 5] = ss;
    __syncthreads();
    float var = (red2[0] + red2[1] + red2[2] + red2[3]) * (1.0f / CD);
    float inv = rsqrtf(var + CEPS);

    float4 gv = reinterpret_cast<const float4*>(g)[tid];
    float4 bv = reinterpret_cast<const float4*>(b)[tid];
    float4 o4;
    o4.x = dx * inv * gv.x + bv.x;
    o4.y = dy * inv * gv.y + bv.y;
    o4.z = dz * inv * gv.z + bv.z;
    o4.w = dw * inv * gv.w + bv.w;
    if (ROUND) {
        o4.x = rna_tf32(o4.x); o4.y = rna_tf32(o4.y);
        o4.z = rna_tf32(o4.z); o4.w = rna_tf32(o4.w);
    }
    reinterpret_cast<float4*>(y + (size_t)row * CD)[tid] = o4;
}

// ------------------------------- TC GEMM core -------------------------------
// C[M=4096, N] = epilogue(A @ B + bias)
// A pre-rounded tf32 in memory; B converted in-loop.
// mode: 0 = bias, 1 = swish (store rounded), 2 = 0.125*(..), 3 = res+,
//       5 = raw accumulator store (split-K partial; bias/res unused)
// BK=32, 2-stage cp.async double buffering.
#define AS_STRIDE 36           // [m][k], pad 32->36 (bank = (4g+tig)%32, distinct)
#define BS_STRIDE 136          // [k][n], pad 128->136 (bank = (8tig+g)%32, distinct)
#define A_STAGE   (128 * AS_STRIDE)   // 4608 floats
#define B_STAGE   (32 * BS_STRIDE)    // 4352 floats
#define SMEM_BYTES ((2 * (A_STAGE + B_STAGE)) * 4)   // 71680 B

#define GEMM_LOAD_STAGE(sbuf, kbase)                                           \
    {                                                                          \
        float* as_ = sm_a + (sbuf) * A_STAGE;                                  \
        float* bs_ = sm_b + (sbuf) * B_STAGE;                                  \
        _Pragma("unroll")                                                      \
        for (int it = 0; it < 4; it++) {                                       \
            int idx = tid + it * 256;                                          \
            cp16(&as_[(idx >> 3) * AS_STRIDE + (idx & 7) * 4],                 \
                 &A[(size_t)(m0 + (idx >> 3)) * lda + (kbase) + (idx & 7) * 4]);\
            cp16(&bs_[(idx >> 5) * BS_STRIDE + (idx & 31) * 4],                \
                 &Bm[(size_t)((kbase) + (idx >> 5)) * N + n0 + (idx & 31) * 4]);\
        }                                                                      \
        asm volatile("cp.async.commit_group;\n");                              \
    }

__device__ __forceinline__ void gemm_core(
    const float* __restrict__ A, const float* __restrict__ Bm,
    const float* __restrict__ bias, const float* __restrict__ res,
    float* __restrict__ C, int N, int K, int lda, int mode)
{
    extern __shared__ float smem[];
    float* sm_a = smem;                 // 2 stages A
    float* sm_b = smem + 2 * A_STAGE;   // 2 stages B

    const int tid  = threadIdx.x;
    const int lane = tid & 31;
    const int warp = tid >> 5;
    const int g    = lane >> 2;
    const int tig  = lane & 3;

    const int m0 = blockIdx.y * 128;
    const int n0 = blockIdx.x * 128;
    const int wm = (warp & 1) * 64;
    const int wn = (warp >> 1) * 32;

    float acc[4][4][4];
    #pragma unroll
    for (int mt = 0; mt < 4; mt++)
        #pragma unroll
        for (int nt = 0; nt < 4; nt++)
            #pragma unroll
            for (int i = 0; i < 4; i++) acc[mt][nt][i] = 0.0f;

    const int niter = K >> 5;           // BK = 32
    GEMM_LOAD_STAGE(0, 0);

    for (int i = 0; i < niter; i++) {
        asm volatile("cp.async.wait_group 0;\n");
        __syncthreads();
        if (i + 1 < niter) GEMM_LOAD_STAGE((i + 1) & 1, (i + 1) << 5);

        const float* as = sm_a + (i & 1) * A_STAGE;
        const float* bs = sm_b + (i & 1) * B_STAGE;
        #pragma unroll
        for (int ks = 0; ks < 4; ks++) {
            const int kk = ks * 8;
            uint32_t bfrag[4][2];
            #pragma unroll
            for (int nt = 0; nt < 4; nt++) {
                int col = wn + nt * 8 + g;
                bfrag[nt][0] = to_tf32(bs[(kk + tig)     * BS_STRIDE + col]);
                bfrag[nt][1] = to_tf32(bs[(kk + tig + 4) * BS_STRIDE + col]);
            }
            #pragma unroll
            for (int mt = 0; mt < 4; mt++) {
                uint32_t afrag[4];
                int r0 = wm + mt * 16 + g;
                afrag[0] = __float_as_uint(as[r0       * AS_STRIDE + kk + tig]);
                afrag[1] = __float_as_uint(as[(r0 + 8) * AS_STRIDE + kk + tig]);
                afrag[2] = __float_as_uint(as[r0       * AS_STRIDE + kk + tig + 4]);
                afrag[3] = __float_as_uint(as[(r0 + 8) * AS_STRIDE + kk + tig + 4]);
                #pragma unroll
                for (int nt = 0; nt < 4; nt++)
                    MMA_TF32(acc[mt][nt], afrag, bfrag[nt]);
            }
        }
    }

    // ----------------------------- epilogue ---------------------------------
    #pragma unroll
    for (int mt = 0; mt < 4; mt++) {
        int r0 = m0 + wm + mt * 16 + g;
        #pragma unroll
        for (int nt = 0; nt < 4; nt++) {
            int cb = n0 + wn + nt * 8 + tig * 2;
            if (mode == 5) {    // raw partial store
                #pragma unroll
                for (int half = 0; half < 2; half++) {
                    int row = r0 + half * 8;
                    float2 o;
                    o.x = acc[mt][nt][half * 2 + 0];
                    o.y = acc[mt][nt][half * 2 + 1];
                    *reinterpret_cast<float2*>(&C[(size_t)row * N + cb]) = o;
                }
                continue;
            }
            float b0 = bias[cb], b1 = bias[cb + 1];
            #pragma unroll
            for (int half = 0; half < 2; half++) {
                int row = r0 + half * 8;
                float c0 = acc[mt][nt][half * 2 + 0] + b0;
                float c1 = acc[mt][nt][half * 2 + 1] + b1;
                if (mode == 1) {
                    c0 *= fsig(c0);
                    c1 *= fsig(c1);
                    c0 = rna_tf32(c0);          // feeds next GEMM only
                    c1 = rna_tf32(c1);
                } else if (mode == 2) {
                    c0 *= 0.125f; c1 *= 0.125f;
                } else if (mode == 3) {
                    const float2 r = *reinterpret_cast<const float2*>(
                        &res[(size_t)row * N + cb]);
                    c0 += r.x; c1 += r.y;
                }
                float2 o; o.x = c0; o.y = c1;
                *reinterpret_cast<float2*>(&C[(size_t)row * N + cb]) = o;
            }
        }
    }
}

__global__ __launch_bounds__(256, 2)
void gemm_tc(const float* __restrict__ A, const float* __restrict__ Bm,
             const float* __restrict__ bias, const float* __restrict__ res,
             float* __restrict__ C, int N, int K, int lda, int mode)
{
    gemm_core(A, Bm, bias, res, C, N, K, lda, mode);
}

// split-K=2 over K (any K divisible by 64): z selects K-half; partials to p0/p1
__global__ __launch_bounds__(256, 2)
void gemm_splitk(const float* __restrict__ A, const float* __restrict__ Bm,
                 float* __restrict__ p0, float* __restrict__ p1,
                 int K, int lda)
{
    int z = blockIdx.z;
    int Kh = K >> 1;
    const float* Ah = A + (size_t)z * Kh;
    const float* Bh = Bm + (size_t)z * Kh * CD;
    float* C = z ? p1 : p0;
    gemm_core(Ah, Bh, nullptr, nullptr, C, CD, Kh, lda, 5);
}

// merged QKV: grid.z selects which projection this CTA computes
__global__ __launch_bounds__(256, 2)
void gemm_qkv(const float* __restrict__ A,
              const float* __restrict__ Bq, const float* __restrict__ Bk,
              const float* __restrict__ Bv,
              const float* __restrict__ bq, const float* __restrict__ bk,
              const float* __restrict__ bv,
              float* __restrict__ Cq, float* __restrict__ Ck,
              float* __restrict__ Cv)
{
    int z = blockIdx.z;
    const float* Bm   = (z == 0) ? Bq : (z == 1) ? Bk : Bv;
    const float* bias = (z == 0) ? bq : (z == 1) ? bk : bv;
    float*       C    = (z == 0) ? Cq : (z == 1) ? Ck : Cv;
    gemm_core(A, Bm, bias, nullptr, C, CD, CD, CD, (z == 0) ? 2 : 0);
}

// split-K combine: C = res + scale*(p0 + p1 + bias); Cr = rna(C) if non-null
__global__ void combine_k(const float* __restrict__ p0, const float* __restrict__ p1,
                          const float* __restrict__ bias, const float* __restrict__ res,
                          float* __restrict__ C, float* __restrict__ Cr, float scale)
{
    int i = blockIdx.x * 256 + threadIdx.x;       // over NTOK*CD/4
    float4 a0 = reinterpret_cast<const float4*>(p0)[i];
    float4 a1 = reinterpret_cast<const float4*>(p1)[i];
    float4 bv = reinterpret_cast<const float4*>(bias)[i & 127];
    float4 rv = reinterpret_cast<const float4*>(res)[i];
    float4 c;
    c.x = rv.x + scale * (a0.x + a1.x + bv.x);
    c.y = rv.y + scale * (a0.y + a1.y + bv.y);
    c.z = rv.z + scale * (a0.z + a1.z + bv.z);
    c.w = rv.w + scale * (a0.w + a1.w + bv.w);
    reinterpret_cast<float4*>(C)[i] = c;
    if (Cr) {
        float4 r;
        r.x = rna_tf32(c.x); r.y = rna_tf32(c.y);
        r.z = rna_tf32(c.z); r.w = rna_tf32(c.w);
        reinterpret_cast<float4*>(Cr)[i] = r;
    }
}

// fused FF2-combine + final LN: h2 = res + 0.5*(p0+p1+bias); out = LN(h2)
__global__ void combine_ln_k(const float* __restrict__ p0, const float* __restrict__ p1,
                             const float* __restrict__ bias, const float* __restrict__ res,
                             const float* __restrict__ lng, const float* __restrict__ lnb,
                             float* __restrict__ out)
{
    int row = blockIdx.x;
    int tid = threadIdx.x;
    size_t base = (size_t)row * CD;

    float4 a0 = reinterpret_cast<const float4*>(p0 + base)[tid];
    float4 a1 = reinterpret_cast<const float4*>(p1 + base)[tid];
    float4 bv = reinterpret_cast<const float4*>(bias)[tid];
    float4 rv = reinterpret_cast<const float4*>(res + base)[tid];
    float4 v;
    v.x = rv.x + 0.5f * (a0.x + a1.x + bv.x);
    v.y = rv.y + 0.5f * (a0.y + a1.y + bv.y);
    v.z = rv.z + 0.5f * (a0.z + a1.z + bv.z);
    v.w = rv.w + 0.5f * (a0.w + a1.w + bv.w);

    __shared__ float red1[4];
    __shared__ float red2[4];

    float s = v.x + v.y + v.z + v.w;
    #pragma unroll
    for (int o = 16; o; o >>= 1) s += __shfl_xor_sync(0xffffffffu, s, o);
    if ((tid & 31) == 0) red1[tid >> 5] = s;
    __syncthreads();
    float mean = (red1[0] + red1[1] + red1[2] + red1[3]) * (1.0f / CD);

    float dx = v.x - mean, dy = v.y - mean, dz = v.z - mean, dw = v.w - mean;
    float ss = dx * dx + dy * dy + dz * dz + dw * dw;
    #pragma unroll
    for (int o = 16; o; o >>= 1) ss += __shfl_xor_sync(0xffffffffu, ss, o);
    if ((tid & 31) == 0) red2[tid >> 5] = ss;
    __syncthreads();
    float var = (red2[0] + red2[1] + red2[2] + red2[3]) * (1.0f / CD);
    float inv = rsqrtf(var + CEPS);

    float4 gv = reinterpret_cast<const float4*>(lng)[tid];
    float4 lb = reinterpret_cast<const float4*>(lnb)[tid];
    float4 o4;
    o4.x = dx * inv * gv.x + lb.x;
    o4.y = dy * inv * gv.y + lb.y;
    o4.z = dz * inv * gv.z + lb.z;
    o4.w = dw * inv * gv.w + lb.w;
    reinterpret_cast<float4*>(out + base)[tid] = o4;
}

// ------------------------------- Attention ---------------------------------
__global__ void attn_k(const float* __restrict__ q, const float* __restrict__ k,
                       const float* __restrict__ v, const float* __restrict__ hin,
                       float* __restrict__ hout, float* __restrict__ probs)
{
    __shared__ float sc[4][CWB + 1];
    int warp = threadIdx.x >> 5;
    int lane = threadIdx.x & 31;
    int item = blockIdx.x * 4 + warp;          // < B*T*H
    int head = item & (CH - 1);
    int bt   = item >> 3;                      // b*T + t
    int t    = bt & (CT - 1);
    int brow = bt - t;                         // b*T

    const float2* qrow = reinterpret_cast<const float2*>(q + (size_t)bt * CD + head * CDH);
    float2 q2 = qrow[lane];

    for (int w = 0; w < CWB; w++) {
        int tk = t + w - CW1;
        float val = -1e9f;
        if (tk >= 0 && tk < CT) {
            const float2* krow =
                reinterpret_cast<const float2*>(k + (size_t)(brow + tk) * CD + head * CDH);
            float2 k2 = krow[lane];
            float p = q2.x * k2.x + q2.y * k2.y;
            #pragma unroll
            for (int o = 16; o; o >>= 1) p += __shfl_xor_sync(0xffffffffu, p, o);
            val = p;
        }
        if (lane == 0) sc[warp][w] = val;
    }
    __syncwarp();

    float m = -1e30f;
    for (int w = lane; w < CWB; w += 32) m = fmaxf(m, sc[warp][w]);
    #pragma unroll
    for (int o = 16; o; o >>= 1) m = fmaxf(m, __shfl_xor_sync(0xffffffffu, m, o));
    float ssum = 0.0f;
    for (int w = lane; w < CWB; w += 32) {
        float e = expf(sc[warp][w] - m);
        sc[warp][w] = e;
        ssum += e;
    }
    #pragma unroll
    for (int o = 16; o; o >>= 1) ssum += __shfl_xor_sync(0xffffffffu, ssum, o);
    float inv = 1.0f / ssum;
    __syncwarp();

    float* prow = probs + (size_t)item * CWB;
    for (int w = lane; w < CWB; w += 32) {
        float p = sc[warp][w] * inv;
        sc[warp][w] = p;
        prow[w] = p;
    }
    __syncwarp();

    float cx = 0.0f, cy = 0.0f;
    for (int w = 0; w < CWB; w++) {
        int tk = t + w - CW1;
        if (tk < 0 || tk >= CT) continue;
        float p = sc[warp][w];
        const float2* vrow =
            reinterpret_cast<const float2*>(v + (size_t)(brow + tk) * CD + head * CDH);
        float2 v2 = vrow[lane];
        cx = fmaf(p, v2.x, cx);
        cy = fmaf(p, v2.y, cy);
    }
    size_t off = (size_t)bt * CD + head * CDH + lane * 2;
    hout[off]     = hin[off]     + cx;
    hout[off + 1] = hin[off + 1] + cy;
}

// ---------------------------------- GLU ------------------------------------
__global__ void glu_k(const float* __restrict__ in, float* __restrict__ out)
{
    int i = blockIdx.x * 256 + threadIdx.x;    // NTOK*CD threads
    int row = i >> 9;
    int col = i & (CD - 1);
    float a = in[(size_t)row * CCE + col];
    float g = in[(size_t)row * CCE + CD + col];
    out[i] = a * fsig(g);
}

// -------------------- depthwise conv + BN + swish ---------------------------
__global__ void dwconv_k(const float* __restrict__ in, const float* __restrict__ w,
                         const float* __restrict__ dwb, const float* __restrict__ bng,
                         const float* __restrict__ bnb, float* __restrict__ out)
{
    int c  = blockIdx.y * 128 + threadIdx.x;
    int bt = blockIdx.x;
    int t  = bt & (CT - 1);
    int brow = bt - t;

    float acc = 0.0f;
    #pragma unroll
    for (int kk = 0; kk < CKS; kk++) {
        int tt = t + kk - (CKS - 1) / 2;
        if (tt >= 0 && tt < CT)
            acc = fmaf(__ldg(&w[kk * CD + c]),
                       __ldg(&in[(size_t)(brow + tt) * CD + c]), acc);
    }
    acc += dwb[c];
    acc = acc * (rsqrtf(1.0f + CEPS) * bng[c]) + bnb[c];
    acc = acc * fsig(acc);             // swish
    out[(size_t)bt * CD + c] = rna_tf32(acc);
}

// ------------------------------ launch -------------------------------------
extern "C" void kernel_launch(void* const* d_in, const int* in_sizes, int n_in,
                              void* d_out, int out_size)
{
    (void)in_sizes; (void)n_in; (void)out_size;
    const float* x          = (const float*)d_in[0];
    const float* ff1_ln_g   = (const float*)d_in[1];
    const float* ff1_ln_b   = (const float*)d_in[2];
    const float* ff1_w1     = (const float*)d_in[3];
    const float* ff1_b1     = (const float*)d_in[4];
    const float* ff1_w2     = (const float*)d_in[5];
    const float* ff1_b2     = (const float*)d_in[6];
    const float* ff2_ln_g   = (const float*)d_in[7];
    const float* ff2_ln_b   = (const float*)d_in[8];
    const float* ff2_w1     = (const float*)d_in[9];
    const float* ff2_b1     = (const float*)d_in[10];
    const float* ff2_w2     = (const float*)d_in[11];
    const float* ff2_b2     = (const float*)d_in[12];
    const float* wq         = (const float*)d_in[13];
    const float* bq         = (const float*)d_in[14];
    const float* wk         = (const float*)d_in[15];
    const float* bk         = (const float*)d_in[16];
    const float* wv         = (const float*)d_in[17];
    const float* bv         = (const float*)d_in[18];
    const float* conv_ln_g  = (const float*)d_in[19];
    const float* conv_ln_b  = (const float*)d_in[20];
    const float* conv_pw1_w = (const float*)d_in[21];
    const float* conv_pw1_b = (const float*)d_in[22];
    const float* conv_dw_w  = (const float*)d_in[23];
    const float* conv_dw_b  = (const float*)d_in[24];
    const float* conv_bn_g  = (const float*)d_in[25];
    const float* conv_bn_b  = (const float*)d_in[26];
    const float* conv_pw2_w = (const float*)d_in[27];
    const float* conv_pw2_b = (const float*)d_in[28];
    const float* final_ln_g = (const float*)d_in[29];
    const float* final_ln_b = (const float*)d_in[30];

    float* out_main  = (float*)d_out;                         // (B,T,D)
    float* out_probs = (float*)d_out + (size_t)NTOK * CD;     // (B,T,H,WB)

    float *ln_, *ff_, *h_, *hr_, *h2_, *q_, *k_, *v_, *ce_, *glu_, *dw_, *p0_, *p1_;
    cudaGetSymbolAddress((void**)&ln_,  g_ln);
    cudaGetSymbolAddress((void**)&ff_,  g_ff);
    cudaGetSymbolAddress((void**)&h_,   g_h);
    cudaGetSymbolAddress((void**)&hr_,  g_hr);
    cudaGetSymbolAddress((void**)&h2_,  g_h2);
    cudaGetSymbolAddress((void**)&q_,   g_q);
    cudaGetSymbolAddress((void**)&k_,   g_k);
    cudaGetSymbolAddress((void**)&v_,   g_v);
    cudaGetSymbolAddress((void**)&ce_,  g_ce);
    cudaGetSymbolAddress((void**)&glu_, g_glu);
    cudaGetSymbolAddress((void**)&dw_,  g_dw);
    cudaGetSymbolAddress((void**)&p0_,  g_p0);
    cudaGetSymbolAddress((void**)&p1_,  g_p1);

    cudaFuncSetAttribute(gemm_tc,     cudaFuncAttributeMaxDynamicSharedMemorySize, SMEM_BYTES);
    cudaFuncSetAttribute(gemm_qkv,    cudaFuncAttributeMaxDynamicSharedMemorySize, SMEM_BYTES);
    cudaFuncSetAttribute(gemm_splitk, cudaFuncAttributeMaxDynamicSharedMemorySize, SMEM_BYTES);

    dim3 blk256(256);
    dim3 gFF1(CFF / 128, NTOK / 128);        // 512 CTAs
    dim3 gCE (CCE / 128, NTOK / 128);        // 256 CTAs
    dim3 gQKV(CD  / 128, NTOK / 128, 3);     // 384 CTAs
    dim3 gDK (CD  / 128, NTOK / 128, 2);     // 256 CTAs (split-K)
    const int nComb = NTOK * CD / 4 / 256;   // 2048 blocks

    // ---- FF1: h = x + 0.5 * ff(x) ----
    ln_k<true><<<NTOK, 128>>>(x, ff1_ln_g, ff1_ln_b, ln_);
    gemm_tc<<<gFF1, blk256, SMEM_BYTES>>>(ln_, ff1_w1, ff1_b1, nullptr, ff_, CFF, CD, CD, 1);
    gemm_splitk<<<gDK, blk256, SMEM_BYTES>>>(ff_, ff1_w2, p0_, p1_, CFF, CFF);
    combine_k<<<nComb, blk256>>>(p0_, p1_, ff1_b2, x, h_, hr_, 0.5f);

    // ---- QKV (one launch; A = rounded h) ----
    gemm_qkv<<<gQKV, blk256, SMEM_BYTES>>>(hr_, wq, wk, wv, bq, bk, bv, q_, k_, v_);

    // ---- attention (h2 = h + ctx; probs -> d_out) ----
    attn_k<<<(NTOK * CH) / 4, 128>>>(q_, k_, v_, h_, h2_, out_probs);

    // ---- conv module: h = h2 + conv(h2) ----
    ln_k<true><<<NTOK, 128>>>(h2_, conv_ln_g, conv_ln_b, ln_);
    gemm_tc<<<gCE, blk256, SMEM_BYTES>>>(ln_, conv_pw1_w, conv_pw1_b, nullptr, ce_, CCE, CD, CD, 0);
    glu_k<<<(NTOK * CD) / 256, blk256>>>(ce_, glu_);
    dwconv_k<<<dim3(NTOK, CD / 128), 128>>>(glu_, conv_dw_w, conv_dw_b,
                                            conv_bn_g, conv_bn_b, dw_);
    gemm_splitk<<<gDK, blk256, SMEM_BYTES>>>(dw_, conv_pw2_w, p0_, p1_, CD, CD);
    combine_k<<<nComb, blk256>>>(p0_, p1_, conv_pw2_b, h2_, h_, nullptr, 1.0f);

    // ---- FF2: h2 = h + 0.5 * ff(h); out = LN(h2) ----
    ln_k<true><<<NTOK, 128>>>(h_, ff2_ln_g, ff2_ln_b, ln_);
    gemm_tc<<<gFF1, blk256, SMEM_BYTES>>>(ln_, ff2_w1, ff2_b1, nullptr, ff_, CFF, CD, CD, 1);
    gemm_splitk<<<gDK, blk256, SMEM_BYTES>>>(ff_, ff2_w2, p0_, p1_, CFF, CFF);
    combine_ln_k<<<NTOK, 128>>>(p0_, p1_, ff2_b2, h_, final_ln_g, final_ln_b, out_main);
}